// round 14
// baseline (speedup 1.0000x reference)
#include <cuda_runtime.h>
#include <cuda_bf16.h>
#include <math.h>
#include <cstdint>

#define BATCH 4
#define CDIM 384
#define NHEADS 8
#define CPH 48
#define NPIX 16384
#define C3 1152

// ================= scratch =================
__device__ float g_qkv1[(size_t)BATCH * C3 * NPIX];
__device__ float g_qkv2[(size_t)BATCH * C3 * NPIX];
__device__ float g_norm[BATCH * 768];
__device__ float g_part[32 * 16 * 2304];
__device__ float g_probs[32 * 2304];
__device__ __nv_bfloat16 g_xT_hi[(size_t)BATCH * NPIX * CDIM];
__device__ __nv_bfloat16 g_xT_lo[(size_t)BATCH * NPIX * CDIM];
__device__ __nv_bfloat16 g_aT_hi[(size_t)BATCH * NPIX * CDIM];
__device__ __nv_bfloat16 g_aT_lo[(size_t)BATCH * NPIX * CDIM];
__device__ __nv_bfloat16 g_wq_hi[C3 * CDIM];
__device__ __nv_bfloat16 g_wq_lo[C3 * CDIM];
__device__ __nv_bfloat16 g_wp_hi[CDIM * CDIM];
__device__ __nv_bfloat16 g_wp_lo[CDIM * CDIM];

// ================= helpers =================
__device__ __forceinline__ uint32_t smem_u32(const void* p) {
    uint32_t a;
    asm("{ .reg .u64 t; cvta.to.shared.u64 t, %1; cvt.u32.u64 %0, t; }" : "=r"(a) : "l"(p));
    return a;
}
__device__ __forceinline__ void cp16(uint32_t s, const void* g) {
    asm volatile("cp.async.cg.shared.global [%0], [%1], 16;" :: "r"(s), "l"(g));
}
__device__ __forceinline__ void mma16816(float* c, const uint32_t* a, uint32_t b0, uint32_t b1) {
    asm volatile(
        "mma.sync.aligned.m16n8k16.row.col.f32.bf16.bf16.f32 "
        "{%0,%1,%2,%3}, {%4,%5,%6,%7}, {%8,%9}, {%0,%1,%2,%3};"
        : "+f"(c[0]), "+f"(c[1]), "+f"(c[2]), "+f"(c[3])
        : "r"(a[0]), "r"(a[1]), "r"(a[2]), "r"(a[3]), "r"(b0), "r"(b1));
}
__device__ __forceinline__ void ldsm4(uint32_t* r, uint32_t addr) {
    asm volatile("ldmatrix.sync.aligned.m8n8.x4.shared.b16 {%0,%1,%2,%3}, [%4];"
                 : "=r"(r[0]), "=r"(r[1]), "=r"(r[2]), "=r"(r[3]) : "r"(addr));
}

// ================= 3xBF16 HMMA GEMM: 128x128 CTA, 4 warps of 64x64, 2-stage =================
// R13 base; second cp.async half moved to mid-kc0 for longer latency cover (no extra barriers).
#define AT 10240
#define STAGE (4 * AT)
#define GEMM_SMEM (2 * STAGE)

__global__ void __launch_bounds__(128, 2) gemm_hmma(
    const __nv_bfloat16* __restrict__ Ah, const __nv_bfloat16* __restrict__ Al,
    const __nv_bfloat16* __restrict__ Bh, const __nv_bfloat16* __restrict__ Bl,
    float* __restrict__ C, size_t strideB, size_t strideC) {
    extern __shared__ char sm[];
    const uint32_t sb = smem_u32(sm);
    const int tid = threadIdx.x;
    const int m0 = blockIdx.x * 128;
    const int n0 = blockIdx.y * 128;
    const __nv_bfloat16* bhp = Bh + blockIdx.z * strideB;
    const __nv_bfloat16* blp = Bl + blockIdx.z * strideB;
    float* Cp = C + blockIdx.z * strideC;

    const int wid = tid >> 5, lane = tid & 31;
    const int wm = (wid & 1) * 64, wn = (wid >> 1) * 64;
    const int qr = lane >> 2, qc = lane & 3;
    const int la = lane & 15, ha = lane >> 4;
    const int lb = (lane & 7) + (lane >> 4) * 8;
    const int mb = (lane >> 3) & 1;

    float acc[4][8][4];
#pragma unroll
    for (int i = 0; i < 4; i++)
#pragma unroll
        for (int j = 0; j < 8; j++)
#pragma unroll
            for (int t = 0; t < 4; t++) acc[i][j][t] = 0.f;

    const int r0 = tid >> 2;
    const int lc = (tid & 3) * 16;

    auto issue_half = [&](int k0, uint32_t bb, int p0) {
#pragma unroll
        for (int p = p0; p < p0 + 2; p++) {
            int row = r0 + p * 32;
            uint32_t so = (uint32_t)row * 80 + lc;
            cp16(bb + so, (const char*)(Ah + (size_t)(m0 + row) * 384 + k0) + lc);
            cp16(bb + AT + so, (const char*)(Al + (size_t)(m0 + row) * 384 + k0) + lc);
            cp16(bb + 2 * AT + so, (const char*)(bhp + (size_t)(n0 + row) * 384 + k0) + lc);
            cp16(bb + 3 * AT + so, (const char*)(blp + (size_t)(n0 + row) * 384 + k0) + lc);
        }
    };

    issue_half(0, sb, 0);
    issue_half(0, sb, 2);
    asm volatile("cp.async.commit_group;");

#pragma unroll 1
    for (int ch = 0; ch < 12; ch++) {
        asm volatile("cp.async.wait_group 0;");
        __syncthreads();

        const uint32_t bufb = sb + (ch & 1) * STAGE;
        const bool pf = ch < 11;
        const uint32_t nb = sb + ((ch + 1) & 1) * STAGE;
        const int k0n = (ch + 1) * 32;

        // ---- kc = 0 ----
        {
            uint32_t bh[4][4], bl[4][4];
#pragma unroll
            for (int jp = 0; jp < 4; jp++) {
                uint32_t br = (uint32_t)(wn + jp * 16 + lb) * 80 + (uint32_t)(mb * 8) * 2;
                ldsm4(bh[jp], bufb + 2 * AT + br);
                ldsm4(bl[jp], bufb + 3 * AT + br);
            }
            if (pf) issue_half(k0n, nb, 0);
#pragma unroll
            for (int mi = 0; mi < 2; mi++) {
                uint32_t ar = (uint32_t)(wm + mi * 16 + la) * 80 + (uint32_t)(ha * 8) * 2;
                uint32_t aH[4], aL[4];
                ldsm4(aH, bufb + ar);
                ldsm4(aL, bufb + AT + ar);
#pragma unroll
                for (int j = 0; j < 8; j++) {
                    uint32_t b0 = bh[j >> 1][(j & 1) * 2], b1 = bh[j >> 1][(j & 1) * 2 + 1];
                    uint32_t c0 = bl[j >> 1][(j & 1) * 2], c1 = bl[j >> 1][(j & 1) * 2 + 1];
                    mma16816(acc[mi][j], aH, b0, b1);
                    mma16816(acc[mi][j], aH, c0, c1);
                    mma16816(acc[mi][j], aL, b0, b1);
                }
            }
            if (pf) {
                issue_half(k0n, nb, 2);
                asm volatile("cp.async.commit_group;");
            }
#pragma unroll
            for (int mi = 2; mi < 4; mi++) {
                uint32_t ar = (uint32_t)(wm + mi * 16 + la) * 80 + (uint32_t)(ha * 8) * 2;
                uint32_t aH[4], aL[4];
                ldsm4(aH, bufb + ar);
                ldsm4(aL, bufb + AT + ar);
#pragma unroll
                for (int j = 0; j < 8; j++) {
                    uint32_t b0 = bh[j >> 1][(j & 1) * 2], b1 = bh[j >> 1][(j & 1) * 2 + 1];
                    uint32_t c0 = bl[j >> 1][(j & 1) * 2], c1 = bl[j >> 1][(j & 1) * 2 + 1];
                    mma16816(acc[mi][j], aH, b0, b1);
                    mma16816(acc[mi][j], aH, c0, c1);
                    mma16816(acc[mi][j], aL, b0, b1);
                }
            }
        }
        // ---- kc = 16 ----
        {
            uint32_t bh[4][4], bl[4][4];
#pragma unroll
            for (int jp = 0; jp < 4; jp++) {
                uint32_t br = (uint32_t)(wn + jp * 16 + lb) * 80 + (uint32_t)(16 + mb * 8) * 2;
                ldsm4(bh[jp], bufb + 2 * AT + br);
                ldsm4(bl[jp], bufb + 3 * AT + br);
            }
#pragma unroll
            for (int mi = 0; mi < 4; mi++) {
                uint32_t ar = (uint32_t)(wm + mi * 16 + la) * 80 + (uint32_t)(16 + ha * 8) * 2;
                uint32_t aH[4], aL[4];
                ldsm4(aH, bufb + ar);
                ldsm4(aL, bufb + AT + ar);
#pragma unroll
                for (int j = 0; j < 8; j++) {
                    uint32_t b0 = bh[j >> 1][(j & 1) * 2], b1 = bh[j >> 1][(j & 1) * 2 + 1];
                    uint32_t c0 = bl[j >> 1][(j & 1) * 2], c1 = bl[j >> 1][(j & 1) * 2 + 1];
                    mma16816(acc[mi][j], aH, b0, b1);
                    mma16816(acc[mi][j], aH, c0, c1);
                    mma16816(acc[mi][j], aL, b0, b1);
                }
            }
        }
    }

#pragma unroll
    for (int mi = 0; mi < 4; mi++) {
        int rr = m0 + wm + mi * 16 + qr;
#pragma unroll
        for (int j = 0; j < 8; j++) {
            int cc = n0 + wn + j * 8 + qc * 2;
            float* cp = Cp + (size_t)rr * NPIX + cc;
            *(float2*)cp = make_float2(acc[mi][j][0], acc[mi][j][1]);
            *(float2*)(cp + (size_t)8 * NPIX) = make_float2(acc[mi][j][2], acc[mi][j][3]);
        }
    }
}

// ================= fp32 -> bf16 hi/lo converters =================
__global__ void cvt_split(const float* __restrict__ in, __nv_bfloat16* __restrict__ hi,
                          __nv_bfloat16* __restrict__ lo, int n) {
    int i = blockIdx.x * 256 + threadIdx.x;
    if (i >= n) return;
    float v = in[i];
    __nv_bfloat16 h = __float2bfloat16_rn(v);
    hi[i] = h;
    lo[i] = __float2bfloat16_rn(v - __bfloat162float(h));
}

__global__ void transpose_split(const float* __restrict__ x, __nv_bfloat16* __restrict__ th,
                                __nv_bfloat16* __restrict__ tl) {
    __shared__ float t[32][33];
    int b = blockIdx.z;
    int n0 = blockIdx.x * 32, c0 = blockIdx.y * 32;
    t[threadIdx.y][threadIdx.x] =
        x[((size_t)b * CDIM + c0 + threadIdx.y) * NPIX + n0 + threadIdx.x];
    __syncthreads();
    float v = t[threadIdx.x][threadIdx.y];
    __nv_bfloat16 h = __float2bfloat16_rn(v);
    size_t o = ((size_t)b * NPIX + n0 + threadIdx.y) * CDIM + c0 + threadIdx.x;
    th[o] = h;
    tl[o] = __float2bfloat16_rn(v - __bfloat162float(h));
}

// ================= channel-per-block dwconv 3x3 + fused row norm =================
__global__ void __launch_bounds__(256) dwconv_chan_norm(
    const float* __restrict__ in, const float* __restrict__ w,
    float* __restrict__ out, float* __restrict__ invn) {
    extern __shared__ float img[];
    const int chan = blockIdx.x;
    const int b = chan / C3, ch = chan % C3;
    const int tid = threadIdx.x;
    const float* ip = in + ((size_t)b * C3 + ch) * NPIX;
    for (int i = tid; i < 4096; i += 256)
        *(float4*)&img[i * 4] = ((const float4*)ip)[i];
    __syncthreads();
    const float* wp = w + ch * 9;
    float w00 = wp[0], w01 = wp[1], w02 = wp[2];
    float w10 = wp[3], w11 = wp[4], w12 = wp[5];
    float w20 = wp[6], w21 = wp[7], w22 = wp[8];
    float* op = out + ((size_t)b * C3 + ch) * NPIX;
    float ss = 0.f;
    for (int i = tid; i < 4096; i += 256) {
        int x4 = (i & 31) * 4, y = i >> 5;
        float o0 = 0.f, o1 = 0.f, o2 = 0.f, o3 = 0.f;
#pragma unroll
        for (int ky = 0; ky < 3; ky++) {
            int yy = y + ky - 1;
            if (yy < 0 || yy > 127) continue;
            const float* rp = img + yy * 128;
            float4 c = *(const float4*)(rp + x4);
            float lft = (x4 > 0) ? rp[x4 - 1] : 0.f;
            float rgt = (x4 < 124) ? rp[x4 + 4] : 0.f;
            float wa = (ky == 0) ? w00 : (ky == 1) ? w10 : w20;
            float wb = (ky == 0) ? w01 : (ky == 1) ? w11 : w21;
            float wc = (ky == 0) ? w02 : (ky == 1) ? w12 : w22;
            o0 += wa * lft + wb * c.x + wc * c.y;
            o1 += wa * c.x + wb * c.y + wc * c.z;
            o2 += wa * c.y + wb * c.z + wc * c.w;
            o3 += wa * c.z + wb * c.w + wc * rgt;
        }
        *(float4*)(op + y * 128 + x4) = make_float4(o0, o1, o2, o3);
        ss += o0 * o0 + o1 * o1 + o2 * o2 + o3 * o3;
    }
    if (ch < 768) {
        __shared__ float red[8];
#pragma unroll
        for (int o = 16; o; o >>= 1) ss += __shfl_down_sync(~0u, ss, o);
        if ((tid & 31) == 0) red[tid >> 5] = ss;
        __syncthreads();
        if (tid < 8) {
            ss = red[tid];
#pragma unroll
            for (int o = 4; o; o >>= 1) ss += __shfl_down_sync(0xffu, ss, o);
            if (tid == 0) invn[b * 768 + ch] = 1.0f / fmaxf(sqrtf(ss), 1e-12f);
        }
    }
}

// ================= fused pos path per 16-row slab: out += dw2(gelu(dw1(v))) =================
// Block: 128 threads, ~20KB smem, one (b, ch, slab) each — high occupancy, no pos1 buffer.
__global__ void __launch_bounds__(128) pos_slab(
    const float* __restrict__ v, const float* __restrict__ w1,
    const float* __restrict__ w2, float* __restrict__ out) {
    __shared__ float inb[20][128];
    __shared__ float mid[18][132];
    const int blk = blockIdx.x;
    const int s = blk & 7;
    const int ch = (blk >> 3) % CDIM;
    const int b = blk / (CDIM * 8);
    const int y0 = s * 16;
    const int tid = threadIdx.x;
    const float* ip = v + ((size_t)b * C3 + 768 + ch) * NPIX;

    // load input rows y0-2 .. y0+17 (zero outside image)
    for (int i = tid; i < 20 * 32; i += 128) {
        int r = i >> 5, c4 = (i & 31) * 4;
        int y = y0 - 2 + r;
        float4 val = (y >= 0 && y <= 127) ? *(const float4*)(ip + y * 128 + c4)
                                          : make_float4(0.f, 0.f, 0.f, 0.f);
        *(float4*)&inb[r][c4] = val;
    }
    __syncthreads();

    // conv1 + gelu -> mid rows y0-1 .. y0+16 (zero outside image)
    {
        const float* wp = w1 + ch * 9;
        float w00 = wp[0], w01 = wp[1], w02 = wp[2];
        float w10 = wp[3], w11 = wp[4], w12 = wp[5];
        float w20 = wp[6], w21 = wp[7], w22 = wp[8];
        for (int i = tid; i < 18 * 32; i += 128) {
            int r = i >> 5, c4 = (i & 31) * 4;
            int m = y0 - 1 + r;
            float o0 = 0.f, o1 = 0.f, o2 = 0.f, o3 = 0.f;
            if (m >= 0 && m <= 127) {
#pragma unroll
                for (int ky = 0; ky < 3; ky++) {
                    int yy = m + ky - 1;
                    if (yy < 0 || yy > 127) continue;  // rows also zero in inb, but skip anyway
                    const float* rp = inb[r + ky];     // inb row r+ky == image row m-1+ky
                    float4 c = *(const float4*)(rp + c4);
                    float lft = (c4 > 0) ? rp[c4 - 1] : 0.f;
                    float rgt = (c4 < 124) ? rp[c4 + 4] : 0.f;
                    float wa = (ky == 0) ? w00 : (ky == 1) ? w10 : w20;
                    float wb = (ky == 0) ? w01 : (ky == 1) ? w11 : w21;
                    float wc = (ky == 0) ? w02 : (ky == 1) ? w12 : w22;
                    o0 += wa * lft + wb * c.x + wc * c.y;
                    o1 += wa * c.x + wb * c.y + wc * c.z;
                    o2 += wa * c.y + wb * c.z + wc * c.w;
                    o3 += wa * c.z + wb * c.w + wc * rgt;
                }
                o0 = 0.5f * o0 * (1.0f + erff(o0 * 0.70710678118654752f));
                o1 = 0.5f * o1 * (1.0f + erff(o1 * 0.70710678118654752f));
                o2 = 0.5f * o2 * (1.0f + erff(o2 * 0.70710678118654752f));
                o3 = 0.5f * o3 * (1.0f + erff(o3 * 0.70710678118654752f));
            }
            mid[r][c4] = o0; mid[r][c4 + 1] = o1;
            mid[r][c4 + 2] = o2; mid[r][c4 + 3] = o3;
        }
    }
    __syncthreads();

    // conv2 rows y0..y0+15, accumulate into out
    {
        const float* wp = w2 + ch * 9;
        float w00 = wp[0], w01 = wp[1], w02 = wp[2];
        float w10 = wp[3], w11 = wp[4], w12 = wp[5];
        float w20 = wp[6], w21 = wp[7], w22 = wp[8];
        float* op = out + ((size_t)b * CDIM + ch) * NPIX;
        for (int i = tid; i < 16 * 32; i += 128) {
            int j = i >> 5, c4 = (i & 31) * 4;
            int y = y0 + j;
            float o0 = 0.f, o1 = 0.f, o2 = 0.f, o3 = 0.f;
#pragma unroll
            for (int ky = 0; ky < 3; ky++) {
                const float* rp = mid[j + ky];  // mid row j+ky == image row y-1+ky (zeros outside)
                float c0 = rp[c4], c1 = rp[c4 + 1], c2 = rp[c4 + 2], c3 = rp[c4 + 3];
                float lft = (c4 > 0) ? rp[c4 - 1] : 0.f;
                float rgt = (c4 < 124) ? rp[c4 + 4] : 0.f;
                float wa = (ky == 0) ? w00 : (ky == 1) ? w10 : w20;
                float wb = (ky == 0) ? w01 : (ky == 1) ? w11 : w21;
                float wc = (ky == 0) ? w02 : (ky == 1) ? w12 : w22;
                o0 += wa * lft + wb * c0 + wc * c1;
                o1 += wa * c0 + wb * c1 + wc * c2;
                o2 += wa * c1 + wb * c2 + wc * c3;
                o3 += wa * c2 + wb * c3 + wc * rgt;
            }
            float4 prev = *(const float4*)(op + y * 128 + c4);
            *(float4*)(op + y * 128 + c4) =
                make_float4(prev.x + o0, prev.y + o1, prev.z + o2, prev.w + o3);
        }
    }
}

// ================= q.k^T partials =================
__global__ void attn_partial(const float* __restrict__ qkv, float* __restrict__ part) {
    __shared__ float qs[48][68];
    __shared__ float ks[48][68];
    const int split = blockIdx.x, h = blockIdx.y, b = blockIdx.z;
    const int tid = threadIdx.x;
    const float* qbase = qkv + ((size_t)b * C3 + h * CPH) * NPIX;
    const float* kbase = qkv + ((size_t)b * C3 + 384 + h * CPH) * NPIX;
    const int tx = tid & 15, ty = tid >> 4;
    const int c0 = ty * 3, d0 = tx * 3;
    float acc[3][3];
#pragma unroll
    for (int i = 0; i < 3; i++)
#pragma unroll
        for (int j = 0; j < 3; j++) acc[i][j] = 0.f;

    for (int chunk = 0; chunk < 16; chunk++) {
        int n0 = split * 1024 + chunk * 64;
        __syncthreads();
#pragma unroll
        for (int r = 0; r < 3; r++) {
            int v = tid + r * 256;
            int row = v >> 4;
            int col = (v & 15) << 2;
            *(float4*)&qs[row][col] = *(const float4*)(qbase + (size_t)row * NPIX + n0 + col);
            *(float4*)&ks[row][col] = *(const float4*)(kbase + (size_t)row * NPIX + n0 + col);
        }
        __syncthreads();
#pragma unroll
        for (int i = 0; i < 64; i += 4) {
            float4 q0 = *(const float4*)&qs[c0][i];
            float4 q1 = *(const float4*)&qs[c0 + 1][i];
            float4 q2 = *(const float4*)&qs[c0 + 2][i];
            float4 k0 = *(const float4*)&ks[d0][i];
            float4 k1 = *(const float4*)&ks[d0 + 1][i];
            float4 k2 = *(const float4*)&ks[d0 + 2][i];
            acc[0][0] += q0.x * k0.x + q0.y * k0.y + q0.z * k0.z + q0.w * k0.w;
            acc[0][1] += q0.x * k1.x + q0.y * k1.y + q0.z * k1.z + q0.w * k1.w;
            acc[0][2] += q0.x * k2.x + q0.y * k2.y + q0.z * k2.z + q0.w * k2.w;
            acc[1][0] += q1.x * k0.x + q1.y * k0.y + q1.z * k0.z + q1.w * k0.w;
            acc[1][1] += q1.x * k1.x + q1.y * k1.y + q1.z * k1.z + q1.w * k1.w;
            acc[1][2] += q1.x * k2.x + q1.y * k2.y + q1.z * k2.z + q1.w * k2.w;
            acc[2][0] += q2.x * k0.x + q2.y * k0.y + q2.z * k0.z + q2.w * k0.w;
            acc[2][1] += q2.x * k1.x + q2.y * k1.y + q2.z * k1.z + q2.w * k1.w;
            acc[2][2] += q2.x * k2.x + q2.y * k2.y + q2.z * k2.z + q2.w * k2.w;
        }
    }
    float* pp = part + ((size_t)((b * NHEADS + h) * 16 + split)) * 2304;
#pragma unroll
    for (int i = 0; i < 3; i++)
#pragma unroll
        for (int j = 0; j < 3; j++) pp[(c0 + i) * 48 + d0 + j] = acc[i][j];
}

// ================= fused: reduce partials -> logits -> dual softmax blend =================
__global__ void attn_finish(const float* __restrict__ part, const float* __restrict__ invn,
                            const float* __restrict__ temp, const int* __restrict__ mask,
                            const float* __restrict__ wb, float* __restrict__ probs) {
    int row = blockIdx.x;
    int c = row % 48;
    int h = (row / 48) % NHEADS;
    int b = row / (48 * NHEADS);
    int bh = b * NHEADS + h;
    int lane = threadIdx.x;
    const int* mp = mask + (h * 48 + c) * 48;
    float inq = invn[b * 768 + h * CPH + c];
    float tmp = temp[h];

    float lg[2];
#pragma unroll
    for (int t = 0; t < 2; t++) {
        int d = lane + t * 32;
        if (d < 48) {
            float s = 0.f;
#pragma unroll
            for (int sp = 0; sp < 16; sp++)
                s += part[((size_t)(bh * 16 + sp)) * 2304 + c * 48 + d];
            lg[t] = s * inq * invn[b * 768 + 384 + h * CPH + d] * tmp;
        } else {
            lg[t] = -INFINITY;
        }
    }
    bool v1ok = lane + 32 < 48;
    float a0 = lg[0], a1 = lg[1];
    float b0 = (mp[lane] == 0) ? -1e9f : a0;
    float b1 = v1ok ? ((mp[lane + 32] == 0) ? -1e9f : a1) : -INFINITY;
    float mA = fmaxf(a0, a1), mB = fmaxf(b0, b1);
#pragma unroll
    for (int o = 16; o; o >>= 1) {
        mA = fmaxf(mA, __shfl_xor_sync(~0u, mA, o));
        mB = fmaxf(mB, __shfl_xor_sync(~0u, mB, o));
    }
    float eA0 = expf(a0 - mA);
    float eA1 = v1ok ? expf(a1 - mA) : 0.f;
    float eB0 = expf(b0 - mB);
    float eB1 = v1ok ? expf(b1 - mB) : 0.f;
    float sA = eA0 + eA1, sB = eB0 + eB1;
#pragma unroll
    for (int o = 16; o; o >>= 1) {
        sA += __shfl_xor_sync(~0u, sA, o);
        sB += __shfl_xor_sync(~0u, sB, o);
    }
    float w0 = wb[0], w1 = wb[1];
    float wm = fmaxf(w0, w1);
    float ew0 = expf(w0 - wm), ew1 = expf(w1 - wm);
    float wsum = ew0 + ew1;
    float blend0 = ew0 / wsum, blend1 = ew1 / wsum;
    float* pp = probs + (size_t)row * 48;
    pp[lane] = blend0 * eA0 / sA + blend1 * eB0 / sB;
    if (v1ok) pp[lane + 32] = blend0 * eA1 / sA + blend1 * eB1 / sB;
}

// ================= out = attn @ v -> transposed bf16 hi/lo (coalesced) =================
__global__ void attnv(const float* __restrict__ probs, const float* __restrict__ qkv2,
                      __nv_bfloat16* __restrict__ th, __nv_bfloat16* __restrict__ tl) {
    __shared__ float a_s[2304];
    __shared__ uint32_t sh[2][128][26];
    const int h = blockIdx.y, b = blockIdx.z;
    const int tid = threadIdx.x;
    const int n0 = blockIdx.x * 128;
    const int n = n0 + tid;
    const float* ap = probs + (size_t)(b * NHEADS + h) * 2304;
    for (int i = tid; i < 2304; i += 128) a_s[i] = ap[i];
    __syncthreads();
    const float* vbase = qkv2 + ((size_t)b * C3 + 768 + h * CPH) * NPIX + n;
    float vr[48];
#pragma unroll
    for (int d = 0; d < 48; d++) vr[d] = vbase[(size_t)d * NPIX];
    float accv[48];
#pragma unroll 4
    for (int c = 0; c < 48; c++) {
        float acc = 0.f;
#pragma unroll
        for (int d = 0; d < 48; d++) acc += a_s[c * 48 + d] * vr[d];
        accv[c] = acc;
    }
#pragma unroll
    for (int c2 = 0; c2 < 24; c2++) {
        float v0 = accv[2 * c2], v1 = accv[2 * c2 + 1];
        __nv_bfloat16 h0 = __float2bfloat16_rn(v0);
        __nv_bfloat16 h1 = __float2bfloat16_rn(v1);
        __nv_bfloat16 l0 = __float2bfloat16_rn(v0 - __bfloat162float(h0));
        __nv_bfloat16 l1 = __float2bfloat16_rn(v1 - __bfloat162float(h1));
        sh[0][tid][c2] = (uint32_t)__bfloat16_as_ushort(h0) |
                         ((uint32_t)__bfloat16_as_ushort(h1) << 16);
        sh[1][tid][c2] = (uint32_t)__bfloat16_as_ushort(l0) |
                         ((uint32_t)__bfloat16_as_ushort(l1) << 16);
    }
    __syncthreads();
    for (int idx = tid; idx < 2 * 128 * 12; idx += 128) {
        int a = idx / (128 * 12);
        int r = (idx / 12) & 127;
        int j = idx % 12;
        uint2 v = *(const uint2*)&sh[a][r][j * 2];
        __nv_bfloat16* base = a ? tl : th;
        *((uint2*)(base + ((size_t)b * NPIX + n0 + r) * CDIM + h * CPH) + j) = v;
    }
}

// ================= launch =================
extern "C" void kernel_launch(void* const* d_in, const int* in_sizes, int n_in,
                              void* d_out, int out_size) {
    const float* x           = (const float*)d_in[0];
    const int*   mask        = (const int*)d_in[1];
    const float* qkv_w       = (const float*)d_in[2];
    const float* dw_w        = (const float*)d_in[3];
    const float* proj_w      = (const float*)d_in[4];
    const float* temperature = (const float*)d_in[5];
    const float* w_blend     = (const float*)d_in[6];
    const float* pos_w1      = (const float*)d_in[7];
    const float* pos_w2      = (const float*)d_in[8];
    float* out = (float*)d_out;

    float *qkv1, *qkv2, *norm, *part, *probs;
    __nv_bfloat16 *xh, *xl, *ah, *al, *wqh, *wql, *wph, *wpl;
    cudaGetSymbolAddress((void**)&qkv1, g_qkv1);
    cudaGetSymbolAddress((void**)&qkv2, g_qkv2);
    cudaGetSymbolAddress((void**)&norm, g_norm);
    cudaGetSymbolAddress((void**)&part, g_part);
    cudaGetSymbolAddress((void**)&probs, g_probs);
    cudaGetSymbolAddress((void**)&xh, g_xT_hi);
    cudaGetSymbolAddress((void**)&xl, g_xT_lo);
    cudaGetSymbolAddress((void**)&ah, g_aT_hi);
    cudaGetSymbolAddress((void**)&al, g_aT_lo);
    cudaGetSymbolAddress((void**)&wqh, g_wq_hi);
    cudaGetSymbolAddress((void**)&wql, g_wq_lo);
    cudaGetSymbolAddress((void**)&wph, g_wp_hi);
    cudaGetSymbolAddress((void**)&wpl, g_wp_lo);

    static bool init_done = false;
    if (!init_done) {
        cudaFuncSetAttribute(gemm_hmma, cudaFuncAttributeMaxDynamicSharedMemorySize, GEMM_SMEM);
        cudaFuncSetAttribute(dwconv_chan_norm, cudaFuncAttributeMaxDynamicSharedMemorySize, 65536);
        init_done = true;
    }

    // 0) operand conversion
    cvt_split<<<(C3 * CDIM + 255) / 256, 256>>>(qkv_w, wqh, wql, C3 * CDIM);
    cvt_split<<<(CDIM * CDIM + 255) / 256, 256>>>(proj_w, wph, wpl, CDIM * CDIM);
    transpose_split<<<dim3(NPIX / 32, CDIM / 32, BATCH), dim3(32, 32)>>>(x, xh, xl);

    // 1) qkv 1x1 conv via HMMA
    gemm_hmma<<<dim3(C3 / 128, NPIX / 128, BATCH), 128, GEMM_SMEM>>>(
        wqh, wql, xh, xl, qkv1, (size_t)NPIX * CDIM, (size_t)C3 * NPIX);

    // 2) depthwise 3x3 + fused q/k row norms
    dwconv_chan_norm<<<BATCH * C3, 256, 65536>>>(qkv1, dw_w, qkv2, norm);

    // 3) q.k^T partials, then fused reduce + dual softmax
    attn_partial<<<dim3(16, NHEADS, BATCH), 256>>>(qkv2, part);
    attn_finish<<<BATCH * NHEADS * 48, 32>>>(part, norm, temperature, mask, w_blend, probs);

    // 4) attn @ v -> transposed bf16 hi/lo
    attnv<<<dim3(NPIX / 128, NHEADS, BATCH), 128>>>(probs, qkv2, ah, al);

    // 5) proj 1x1 conv via HMMA (writes d_out)
    gemm_hmma<<<dim3(CDIM / 128, NPIX / 128, BATCH), 128, GEMM_SMEM>>>(
        wph, wpl, ah, al, out, (size_t)NPIX * CDIM, (size_t)CDIM * NPIX);

    // 6) fused pos path (slab), adds into d_out
    pos_slab<<<BATCH * CDIM * 8, 128>>>(qkv2, pos_w1, pos_w2, out);
}

// round 15
// speedup vs baseline: 1.0311x; 1.0311x over previous
#include <cuda_runtime.h>
#include <cuda_bf16.h>
#include <math.h>
#include <cstdint>

#define BATCH 4
#define CDIM 384
#define NHEADS 8
#define CPH 48
#define NPIX 16384
#define C3 1152

// ================= scratch =================
__device__ float g_qkv1[(size_t)BATCH * C3 * NPIX];
__device__ float g_qkv2[(size_t)BATCH * C3 * NPIX];
__device__ float g_norm[BATCH * 768];
__device__ float g_part[32 * 16 * 2304];
__device__ float g_probs[32 * 2304];
__device__ __nv_bfloat16 g_xT_hi[(size_t)BATCH * NPIX * CDIM];
__device__ __nv_bfloat16 g_xT_lo[(size_t)BATCH * NPIX * CDIM];
__device__ __nv_bfloat16 g_aT_hi[(size_t)BATCH * NPIX * CDIM];
__device__ __nv_bfloat16 g_aT_lo[(size_t)BATCH * NPIX * CDIM];
__device__ __nv_bfloat16 g_wq_hi[C3 * CDIM];
__device__ __nv_bfloat16 g_wq_lo[C3 * CDIM];
__device__ __nv_bfloat16 g_wp_hi[CDIM * CDIM];
__device__ __nv_bfloat16 g_wp_lo[CDIM * CDIM];

// ================= helpers =================
__device__ __forceinline__ uint32_t smem_u32(const void* p) {
    uint32_t a;
    asm("{ .reg .u64 t; cvta.to.shared.u64 t, %1; cvt.u32.u64 %0, t; }" : "=r"(a) : "l"(p));
    return a;
}
__device__ __forceinline__ void cp16(uint32_t s, const void* g) {
    asm volatile("cp.async.cg.shared.global [%0], [%1], 16;" :: "r"(s), "l"(g));
}
__device__ __forceinline__ void mma16816(float* c, const uint32_t* a, uint32_t b0, uint32_t b1) {
    asm volatile(
        "mma.sync.aligned.m16n8k16.row.col.f32.bf16.bf16.f32 "
        "{%0,%1,%2,%3}, {%4,%5,%6,%7}, {%8,%9}, {%0,%1,%2,%3};"
        : "+f"(c[0]), "+f"(c[1]), "+f"(c[2]), "+f"(c[3])
        : "r"(a[0]), "r"(a[1]), "r"(a[2]), "r"(a[3]), "r"(b0), "r"(b1));
}
__device__ __forceinline__ void ldsm4(uint32_t* r, uint32_t addr) {
    asm volatile("ldmatrix.sync.aligned.m8n8.x4.shared.b16 {%0,%1,%2,%3}, [%4];"
                 : "=r"(r[0]), "=r"(r[1]), "=r"(r[2]), "=r"(r[3]) : "r"(addr));
}

// ================= 3xBF16 HMMA GEMM: 128x128 CTA, 4 warps of 64x64, 2-stage =================
// R13 proven schedule: single barrier per chunk, cp.async spread into kc=0 compute.
#define AT 10240
#define STAGE (4 * AT)
#define GEMM_SMEM (2 * STAGE)

__global__ void __launch_bounds__(128, 2) gemm_hmma(
    const __nv_bfloat16* __restrict__ Ah, const __nv_bfloat16* __restrict__ Al,
    const __nv_bfloat16* __restrict__ Bh, const __nv_bfloat16* __restrict__ Bl,
    float* __restrict__ C, size_t strideB, size_t strideC) {
    extern __shared__ char sm[];
    const uint32_t sb = smem_u32(sm);
    const int tid = threadIdx.x;
    const int m0 = blockIdx.x * 128;
    const int n0 = blockIdx.y * 128;
    const __nv_bfloat16* bhp = Bh + blockIdx.z * strideB;
    const __nv_bfloat16* blp = Bl + blockIdx.z * strideB;
    float* Cp = C + blockIdx.z * strideC;

    const int wid = tid >> 5, lane = tid & 31;
    const int wm = (wid & 1) * 64, wn = (wid >> 1) * 64;
    const int qr = lane >> 2, qc = lane & 3;
    const int la = lane & 15, ha = lane >> 4;
    const int lb = (lane & 7) + (lane >> 4) * 8;
    const int mb = (lane >> 3) & 1;

    float acc[4][8][4];
#pragma unroll
    for (int i = 0; i < 4; i++)
#pragma unroll
        for (int j = 0; j < 8; j++)
#pragma unroll
            for (int t = 0; t < 4; t++) acc[i][j][t] = 0.f;

    const int r0 = tid >> 2;
    const int lc = (tid & 3) * 16;

    auto issue_half = [&](int k0, uint32_t bb, int p0) {
#pragma unroll
        for (int p = p0; p < p0 + 2; p++) {
            int row = r0 + p * 32;
            uint32_t so = (uint32_t)row * 80 + lc;
            cp16(bb + so, (const char*)(Ah + (size_t)(m0 + row) * 384 + k0) + lc);
            cp16(bb + AT + so, (const char*)(Al + (size_t)(m0 + row) * 384 + k0) + lc);
            cp16(bb + 2 * AT + so, (const char*)(bhp + (size_t)(n0 + row) * 384 + k0) + lc);
            cp16(bb + 3 * AT + so, (const char*)(blp + (size_t)(n0 + row) * 384 + k0) + lc);
        }
    };

    issue_half(0, sb, 0);
    issue_half(0, sb, 2);
    asm volatile("cp.async.commit_group;");

#pragma unroll 1
    for (int ch = 0; ch < 12; ch++) {
        asm volatile("cp.async.wait_group 0;");
        __syncthreads();

        const uint32_t bufb = sb + (ch & 1) * STAGE;
        const bool pf = ch < 11;
        const uint32_t nb = sb + ((ch + 1) & 1) * STAGE;
        const int k0n = (ch + 1) * 32;

        // ---- kc = 0 ----
        {
            uint32_t bh[4][4], bl[4][4];
#pragma unroll
            for (int jp = 0; jp < 4; jp++) {
                uint32_t br = (uint32_t)(wn + jp * 16 + lb) * 80 + (uint32_t)(mb * 8) * 2;
                ldsm4(bh[jp], bufb + 2 * AT + br);
                ldsm4(bl[jp], bufb + 3 * AT + br);
            }
            if (pf) issue_half(k0n, nb, 0);
#pragma unroll
            for (int mi = 0; mi < 4; mi++) {
                uint32_t ar = (uint32_t)(wm + mi * 16 + la) * 80 + (uint32_t)(ha * 8) * 2;
                uint32_t aH[4], aL[4];
                ldsm4(aH, bufb + ar);
                ldsm4(aL, bufb + AT + ar);
#pragma unroll
                for (int j = 0; j < 8; j++) {
                    uint32_t b0 = bh[j >> 1][(j & 1) * 2], b1 = bh[j >> 1][(j & 1) * 2 + 1];
                    uint32_t c0 = bl[j >> 1][(j & 1) * 2], c1 = bl[j >> 1][(j & 1) * 2 + 1];
                    mma16816(acc[mi][j], aH, b0, b1);
                    mma16816(acc[mi][j], aH, c0, c1);
                    mma16816(acc[mi][j], aL, b0, b1);
                }
            }
            if (pf) {
                issue_half(k0n, nb, 2);
                asm volatile("cp.async.commit_group;");
            }
        }
        // ---- kc = 16 ----
        {
            uint32_t bh[4][4], bl[4][4];
#pragma unroll
            for (int jp = 0; jp < 4; jp++) {
                uint32_t br = (uint32_t)(wn + jp * 16 + lb) * 80 + (uint32_t)(16 + mb * 8) * 2;
                ldsm4(bh[jp], bufb + 2 * AT + br);
                ldsm4(bl[jp], bufb + 3 * AT + br);
            }
#pragma unroll
            for (int mi = 0; mi < 4; mi++) {
                uint32_t ar = (uint32_t)(wm + mi * 16 + la) * 80 + (uint32_t)(16 + ha * 8) * 2;
                uint32_t aH[4], aL[4];
                ldsm4(aH, bufb + ar);
                ldsm4(aL, bufb + AT + ar);
#pragma unroll
                for (int j = 0; j < 8; j++) {
                    uint32_t b0 = bh[j >> 1][(j & 1) * 2], b1 = bh[j >> 1][(j & 1) * 2 + 1];
                    uint32_t c0 = bl[j >> 1][(j & 1) * 2], c1 = bl[j >> 1][(j & 1) * 2 + 1];
                    mma16816(acc[mi][j], aH, b0, b1);
                    mma16816(acc[mi][j], aH, c0, c1);
                    mma16816(acc[mi][j], aL, b0, b1);
                }
            }
        }
    }

#pragma unroll
    for (int mi = 0; mi < 4; mi++) {
        int rr = m0 + wm + mi * 16 + qr;
#pragma unroll
        for (int j = 0; j < 8; j++) {
            int cc = n0 + wn + j * 8 + qc * 2;
            float* cp = Cp + (size_t)rr * NPIX + cc;
            *(float2*)cp = make_float2(acc[mi][j][0], acc[mi][j][1]);
            *(float2*)(cp + (size_t)8 * NPIX) = make_float2(acc[mi][j][2], acc[mi][j][3]);
        }
    }
}

// ================= fp32 -> bf16 hi/lo converters =================
__global__ void cvt_split(const float* __restrict__ in, __nv_bfloat16* __restrict__ hi,
                          __nv_bfloat16* __restrict__ lo, int n) {
    int i = blockIdx.x * 256 + threadIdx.x;
    if (i >= n) return;
    float v = in[i];
    __nv_bfloat16 h = __float2bfloat16_rn(v);
    hi[i] = h;
    lo[i] = __float2bfloat16_rn(v - __bfloat162float(h));
}

__global__ void transpose_split(const float* __restrict__ x, __nv_bfloat16* __restrict__ th,
                                __nv_bfloat16* __restrict__ tl) {
    __shared__ float t[32][33];
    int b = blockIdx.z;
    int n0 = blockIdx.x * 32, c0 = blockIdx.y * 32;
    t[threadIdx.y][threadIdx.x] =
        x[((size_t)b * CDIM + c0 + threadIdx.y) * NPIX + n0 + threadIdx.x];
    __syncthreads();
    float v = t[threadIdx.x][threadIdx.y];
    __nv_bfloat16 h = __float2bfloat16_rn(v);
    size_t o = ((size_t)b * NPIX + n0 + threadIdx.y) * CDIM + c0 + threadIdx.x;
    th[o] = h;
    tl[o] = __float2bfloat16_rn(v - __bfloat162float(h));
}

// ================= channel-per-block dwconv 3x3 + fused row norm =================
__global__ void __launch_bounds__(256) dwconv_chan_norm(
    const float* __restrict__ in, const float* __restrict__ w,
    float* __restrict__ out, float* __restrict__ invn) {
    extern __shared__ float img[];
    const int chan = blockIdx.x;
    const int b = chan / C3, ch = chan % C3;
    const int tid = threadIdx.x;
    const float* ip = in + ((size_t)b * C3 + ch) * NPIX;
    for (int i = tid; i < 4096; i += 256)
        *(float4*)&img[i * 4] = ((const float4*)ip)[i];
    __syncthreads();
    const float* wp = w + ch * 9;
    float w00 = wp[0], w01 = wp[1], w02 = wp[2];
    float w10 = wp[3], w11 = wp[4], w12 = wp[5];
    float w20 = wp[6], w21 = wp[7], w22 = wp[8];
    float* op = out + ((size_t)b * C3 + ch) * NPIX;
    float ss = 0.f;
    for (int i = tid; i < 4096; i += 256) {
        int x4 = (i & 31) * 4, y = i >> 5;
        float o0 = 0.f, o1 = 0.f, o2 = 0.f, o3 = 0.f;
#pragma unroll
        for (int ky = 0; ky < 3; ky++) {
            int yy = y + ky - 1;
            if (yy < 0 || yy > 127) continue;
            const float* rp = img + yy * 128;
            float4 c = *(const float4*)(rp + x4);
            float lft = (x4 > 0) ? rp[x4 - 1] : 0.f;
            float rgt = (x4 < 124) ? rp[x4 + 4] : 0.f;
            float wa = (ky == 0) ? w00 : (ky == 1) ? w10 : w20;
            float wb = (ky == 0) ? w01 : (ky == 1) ? w11 : w21;
            float wc = (ky == 0) ? w02 : (ky == 1) ? w12 : w22;
            o0 += wa * lft + wb * c.x + wc * c.y;
            o1 += wa * c.x + wb * c.y + wc * c.z;
            o2 += wa * c.y + wb * c.z + wc * c.w;
            o3 += wa * c.z + wb * c.w + wc * rgt;
        }
        *(float4*)(op + y * 128 + x4) = make_float4(o0, o1, o2, o3);
        ss += o0 * o0 + o1 * o1 + o2 * o2 + o3 * o3;
    }
    if (ch < 768) {
        __shared__ float red[8];
#pragma unroll
        for (int o = 16; o; o >>= 1) ss += __shfl_down_sync(~0u, ss, o);
        if ((tid & 31) == 0) red[tid >> 5] = ss;
        __syncthreads();
        if (tid < 8) {
            ss = red[tid];
#pragma unroll
            for (int o = 4; o; o >>= 1) ss += __shfl_down_sync(0xffu, ss, o);
            if (tid == 0) invn[b * 768 + ch] = 1.0f / fmaxf(sqrtf(ss), 1e-12f);
        }
    }
}

// ================= fused pos path per 16-row slab: out += dw2(gelu(dw1(v))) =================
__global__ void __launch_bounds__(128) pos_slab(
    const float* __restrict__ v, const float* __restrict__ w1,
    const float* __restrict__ w2, float* __restrict__ out) {
    __shared__ float inb[20][128];
    __shared__ float mid[18][132];
    const int blk = blockIdx.x;
    const int s = blk & 7;
    const int ch = (blk >> 3) % CDIM;
    const int b = blk / (CDIM * 8);
    const int y0 = s * 16;
    const int tid = threadIdx.x;
    const float* ip = v + ((size_t)b * C3 + 768 + ch) * NPIX;

    for (int i = tid; i < 20 * 32; i += 128) {
        int r = i >> 5, c4 = (i & 31) * 4;
        int y = y0 - 2 + r;
        float4 val = (y >= 0 && y <= 127) ? *(const float4*)(ip + y * 128 + c4)
                                          : make_float4(0.f, 0.f, 0.f, 0.f);
        *(float4*)&inb[r][c4] = val;
    }
    __syncthreads();

    {
        const float* wp = w1 + ch * 9;
        float w00 = wp[0], w01 = wp[1], w02 = wp[2];
        float w10 = wp[3], w11 = wp[4], w12 = wp[5];
        float w20 = wp[6], w21 = wp[7], w22 = wp[8];
        for (int i = tid; i < 18 * 32; i += 128) {
            int r = i >> 5, c4 = (i & 31) * 4;
            int m = y0 - 1 + r;
            float o0 = 0.f, o1 = 0.f, o2 = 0.f, o3 = 0.f;
            if (m >= 0 && m <= 127) {
#pragma unroll
                for (int ky = 0; ky < 3; ky++) {
                    int yy = m + ky - 1;
                    if (yy < 0 || yy > 127) continue;
                    const float* rp = inb[r + ky];
                    float4 c = *(const float4*)(rp + c4);
                    float lft = (c4 > 0) ? rp[c4 - 1] : 0.f;
                    float rgt = (c4 < 124) ? rp[c4 + 4] : 0.f;
                    float wa = (ky == 0) ? w00 : (ky == 1) ? w10 : w20;
                    float wb = (ky == 0) ? w01 : (ky == 1) ? w11 : w21;
                    float wc = (ky == 0) ? w02 : (ky == 1) ? w12 : w22;
                    o0 += wa * lft + wb * c.x + wc * c.y;
                    o1 += wa * c.x + wb * c.y + wc * c.z;
                    o2 += wa * c.y + wb * c.z + wc * c.w;
                    o3 += wa * c.z + wb * c.w + wc * rgt;
                }
                o0 = 0.5f * o0 * (1.0f + erff(o0 * 0.70710678118654752f));
                o1 = 0.5f * o1 * (1.0f + erff(o1 * 0.70710678118654752f));
                o2 = 0.5f * o2 * (1.0f + erff(o2 * 0.70710678118654752f));
                o3 = 0.5f * o3 * (1.0f + erff(o3 * 0.70710678118654752f));
            }
            mid[r][c4] = o0; mid[r][c4 + 1] = o1;
            mid[r][c4 + 2] = o2; mid[r][c4 + 3] = o3;
        }
    }
    __syncthreads();

    {
        const float* wp = w2 + ch * 9;
        float w00 = wp[0], w01 = wp[1], w02 = wp[2];
        float w10 = wp[3], w11 = wp[4], w12 = wp[5];
        float w20 = wp[6], w21 = wp[7], w22 = wp[8];
        float* op = out + ((size_t)b * CDIM + ch) * NPIX;
        for (int i = tid; i < 16 * 32; i += 128) {
            int j = i >> 5, c4 = (i & 31) * 4;
            int y = y0 + j;
            float o0 = 0.f, o1 = 0.f, o2 = 0.f, o3 = 0.f;
#pragma unroll
            for (int ky = 0; ky < 3; ky++) {
                const float* rp = mid[j + ky];
                float c0 = rp[c4], c1 = rp[c4 + 1], c2 = rp[c4 + 2], c3 = rp[c4 + 3];
                float lft = (c4 > 0) ? rp[c4 - 1] : 0.f;
                float rgt = (c4 < 124) ? rp[c4 + 4] : 0.f;
                float wa = (ky == 0) ? w00 : (ky == 1) ? w10 : w20;
                float wb = (ky == 0) ? w01 : (ky == 1) ? w11 : w21;
                float wc = (ky == 0) ? w02 : (ky == 1) ? w12 : w22;
                o0 += wa * lft + wb * c0 + wc * c1;
                o1 += wa * c0 + wb * c1 + wc * c2;
                o2 += wa * c1 + wb * c2 + wc * c3;
                o3 += wa * c2 + wb * c3 + wc * rgt;
            }
            float4 prev = *(const float4*)(op + y * 128 + c4);
            *(float4*)(op + y * 128 + c4) =
                make_float4(prev.x + o0, prev.y + o1, prev.z + o2, prev.w + o3);
        }
    }
}

// ================= q.k^T partials =================
__global__ void attn_partial(const float* __restrict__ qkv, float* __restrict__ part) {
    __shared__ float qs[48][68];
    __shared__ float ks[48][68];
    const int split = blockIdx.x, h = blockIdx.y, b = blockIdx.z;
    const int tid = threadIdx.x;
    const float* qbase = qkv + ((size_t)b * C3 + h * CPH) * NPIX;
    const float* kbase = qkv + ((size_t)b * C3 + 384 + h * CPH) * NPIX;
    const int tx = tid & 15, ty = tid >> 4;
    const int c0 = ty * 3, d0 = tx * 3;
    float acc[3][3];
#pragma unroll
    for (int i = 0; i < 3; i++)
#pragma unroll
        for (int j = 0; j < 3; j++) acc[i][j] = 0.f;

    for (int chunk = 0; chunk < 16; chunk++) {
        int n0 = split * 1024 + chunk * 64;
        __syncthreads();
#pragma unroll
        for (int r = 0; r < 3; r++) {
            int v = tid + r * 256;
            int row = v >> 4;
            int col = (v & 15) << 2;
            *(float4*)&qs[row][col] = *(const float4*)(qbase + (size_t)row * NPIX + n0 + col);
            *(float4*)&ks[row][col] = *(const float4*)(kbase + (size_t)row * NPIX + n0 + col);
        }
        __syncthreads();
#pragma unroll
        for (int i = 0; i < 64; i += 4) {
            float4 q0 = *(const float4*)&qs[c0][i];
            float4 q1 = *(const float4*)&qs[c0 + 1][i];
            float4 q2 = *(const float4*)&qs[c0 + 2][i];
            float4 k0 = *(const float4*)&ks[d0][i];
            float4 k1 = *(const float4*)&ks[d0 + 1][i];
            float4 k2 = *(const float4*)&ks[d0 + 2][i];
            acc[0][0] += q0.x * k0.x + q0.y * k0.y + q0.z * k0.z + q0.w * k0.w;
            acc[0][1] += q0.x * k1.x + q0.y * k1.y + q0.z * k1.z + q0.w * k1.w;
            acc[0][2] += q0.x * k2.x + q0.y * k2.y + q0.z * k2.z + q0.w * k2.w;
            acc[1][0] += q1.x * k0.x + q1.y * k0.y + q1.z * k0.z + q1.w * k0.w;
            acc[1][1] += q1.x * k1.x + q1.y * k1.y + q1.z * k1.z + q1.w * k1.w;
            acc[1][2] += q1.x * k2.x + q1.y * k2.y + q1.z * k2.z + q1.w * k2.w;
            acc[2][0] += q2.x * k0.x + q2.y * k0.y + q2.z * k0.z + q2.w * k0.w;
            acc[2][1] += q2.x * k1.x + q2.y * k1.y + q2.z * k1.z + q2.w * k1.w;
            acc[2][2] += q2.x * k2.x + q2.y * k2.y + q2.z * k2.z + q2.w * k2.w;
        }
    }
    float* pp = part + ((size_t)((b * NHEADS + h) * 16 + split)) * 2304;
#pragma unroll
    for (int i = 0; i < 3; i++)
#pragma unroll
        for (int j = 0; j < 3; j++) pp[(c0 + i) * 48 + d0 + j] = acc[i][j];
}

// ================= fused: reduce partials -> logits -> dual softmax blend =================
__global__ void attn_finish(const float* __restrict__ part, const float* __restrict__ invn,
                            const float* __restrict__ temp, const int* __restrict__ mask,
                            const float* __restrict__ wb, float* __restrict__ probs) {
    int row = blockIdx.x;
    int c = row % 48;
    int h = (row / 48) % NHEADS;
    int b = row / (48 * NHEADS);
    int bh = b * NHEADS + h;
    int lane = threadIdx.x;
    const int* mp = mask + (h * 48 + c) * 48;
    float inq = invn[b * 768 + h * CPH + c];
    float tmp = temp[h];

    float lg[2];
#pragma unroll
    for (int t = 0; t < 2; t++) {
        int d = lane + t * 32;
        if (d < 48) {
            float s = 0.f;
#pragma unroll
            for (int sp = 0; sp < 16; sp++)
                s += part[((size_t)(bh * 16 + sp)) * 2304 + c * 48 + d];
            lg[t] = s * inq * invn[b * 768 + 384 + h * CPH + d] * tmp;
        } else {
            lg[t] = -INFINITY;
        }
    }
    bool v1ok = lane + 32 < 48;
    float a0 = lg[0], a1 = lg[1];
    float b0 = (mp[lane] == 0) ? -1e9f : a0;
    float b1 = v1ok ? ((mp[lane + 32] == 0) ? -1e9f : a1) : -INFINITY;
    float mA = fmaxf(a0, a1), mB = fmaxf(b0, b1);
#pragma unroll
    for (int o = 16; o; o >>= 1) {
        mA = fmaxf(mA, __shfl_xor_sync(~0u, mA, o));
        mB = fmaxf(mB, __shfl_xor_sync(~0u, mB, o));
    }
    float eA0 = expf(a0 - mA);
    float eA1 = v1ok ? expf(a1 - mA) : 0.f;
    float eB0 = expf(b0 - mB);
    float eB1 = v1ok ? expf(b1 - mB) : 0.f;
    float sA = eA0 + eA1, sB = eB0 + eB1;
#pragma unroll
    for (int o = 16; o; o >>= 1) {
        sA += __shfl_xor_sync(~0u, sA, o);
        sB += __shfl_xor_sync(~0u, sB, o);
    }
    float w0 = wb[0], w1 = wb[1];
    float wm = fmaxf(w0, w1);
    float ew0 = expf(w0 - wm), ew1 = expf(w1 - wm);
    float wsum = ew0 + ew1;
    float blend0 = ew0 / wsum, blend1 = ew1 / wsum;
    float* pp = probs + (size_t)row * 48;
    pp[lane] = blend0 * eA0 / sA + blend1 * eB0 / sB;
    if (v1ok) pp[lane + 32] = blend0 * eA1 / sA + blend1 * eB1 / sB;
}

// ================= out = attn @ v -> transposed bf16 hi/lo (coalesced) =================
__global__ void attnv(const float* __restrict__ probs, const float* __restrict__ qkv2,
                      __nv_bfloat16* __restrict__ th, __nv_bfloat16* __restrict__ tl) {
    __shared__ float a_s[2304];
    __shared__ uint32_t sh[2][128][26];
    const int h = blockIdx.y, b = blockIdx.z;
    const int tid = threadIdx.x;
    const int n0 = blockIdx.x * 128;
    const int n = n0 + tid;
    const float* ap = probs + (size_t)(b * NHEADS + h) * 2304;
    for (int i = tid; i < 2304; i += 128) a_s[i] = ap[i];
    __syncthreads();
    const float* vbase = qkv2 + ((size_t)b * C3 + 768 + h * CPH) * NPIX + n;
    float vr[48];
#pragma unroll
    for (int d = 0; d < 48; d++) vr[d] = vbase[(size_t)d * NPIX];
    float accv[48];
#pragma unroll 4
    for (int c = 0; c < 48; c++) {
        float acc = 0.f;
#pragma unroll
        for (int d = 0; d < 48; d++) acc += a_s[c * 48 + d] * vr[d];
        accv[c] = acc;
    }
#pragma unroll
    for (int c2 = 0; c2 < 24; c2++) {
        float v0 = accv[2 * c2], v1 = accv[2 * c2 + 1];
        __nv_bfloat16 h0 = __float2bfloat16_rn(v0);
        __nv_bfloat16 h1 = __float2bfloat16_rn(v1);
        __nv_bfloat16 l0 = __float2bfloat16_rn(v0 - __bfloat162float(h0));
        __nv_bfloat16 l1 = __float2bfloat16_rn(v1 - __bfloat162float(h1));
        sh[0][tid][c2] = (uint32_t)__bfloat16_as_ushort(h0) |
                         ((uint32_t)__bfloat16_as_ushort(h1) << 16);
        sh[1][tid][c2] = (uint32_t)__bfloat16_as_ushort(l0) |
                         ((uint32_t)__bfloat16_as_ushort(l1) << 16);
    }
    __syncthreads();
    for (int idx = tid; idx < 2 * 128 * 12; idx += 128) {
        int a = idx / (128 * 12);
        int r = (idx / 12) & 127;
        int j = idx % 12;
        uint2 v = *(const uint2*)&sh[a][r][j * 2];
        __nv_bfloat16* base = a ? tl : th;
        *((uint2*)(base + ((size_t)b * NPIX + n0 + r) * CDIM + h * CPH) + j) = v;
    }
}

// ================= launch =================
extern "C" void kernel_launch(void* const* d_in, const int* in_sizes, int n_in,
                              void* d_out, int out_size) {
    const float* x           = (const float*)d_in[0];
    const int*   mask        = (const int*)d_in[1];
    const float* qkv_w       = (const float*)d_in[2];
    const float* dw_w        = (const float*)d_in[3];
    const float* proj_w      = (const float*)d_in[4];
    const float* temperature = (const float*)d_in[5];
    const float* w_blend     = (const float*)d_in[6];
    const float* pos_w1      = (const float*)d_in[7];
    const float* pos_w2      = (const float*)d_in[8];
    float* out = (float*)d_out;

    float *qkv1, *qkv2, *norm, *part, *probs;
    __nv_bfloat16 *xh, *xl, *ah, *al, *wqh, *wql, *wph, *wpl;
    cudaGetSymbolAddress((void**)&qkv1, g_qkv1);
    cudaGetSymbolAddress((void**)&qkv2, g_qkv2);
    cudaGetSymbolAddress((void**)&norm, g_norm);
    cudaGetSymbolAddress((void**)&part, g_part);
    cudaGetSymbolAddress((void**)&probs, g_probs);
    cudaGetSymbolAddress((void**)&xh, g_xT_hi);
    cudaGetSymbolAddress((void**)&xl, g_xT_lo);
    cudaGetSymbolAddress((void**)&ah, g_aT_hi);
    cudaGetSymbolAddress((void**)&al, g_aT_lo);
    cudaGetSymbolAddress((void**)&wqh, g_wq_hi);
    cudaGetSymbolAddress((void**)&wql, g_wq_lo);
    cudaGetSymbolAddress((void**)&wph, g_wp_hi);
    cudaGetSymbolAddress((void**)&wpl, g_wp_lo);

    static bool init_done = false;
    if (!init_done) {
        cudaFuncSetAttribute(gemm_hmma, cudaFuncAttributeMaxDynamicSharedMemorySize, GEMM_SMEM);
        cudaFuncSetAttribute(dwconv_chan_norm, cudaFuncAttributeMaxDynamicSharedMemorySize, 65536);
        init_done = true;
    }

    // 0) operand conversion
    cvt_split<<<(C3 * CDIM + 255) / 256, 256>>>(qkv_w, wqh, wql, C3 * CDIM);
    cvt_split<<<(CDIM * CDIM + 255) / 256, 256>>>(proj_w, wph, wpl, CDIM * CDIM);
    transpose_split<<<dim3(NPIX / 32, CDIM / 32, BATCH), dim3(32, 32)>>>(x, xh, xl);

    // 1) qkv 1x1 conv via HMMA
    gemm_hmma<<<dim3(C3 / 128, NPIX / 128, BATCH), 128, GEMM_SMEM>>>(
        wqh, wql, xh, xl, qkv1, (size_t)NPIX * CDIM, (size_t)C3 * NPIX);

    // 2) depthwise 3x3 + fused q/k row norms
    dwconv_chan_norm<<<BATCH * C3, 256, 65536>>>(qkv1, dw_w, qkv2, norm);

    // 3) q.k^T partials, then fused reduce + dual softmax
    attn_partial<<<dim3(16, NHEADS, BATCH), 256>>>(qkv2, part);
    attn_finish<<<BATCH * NHEADS * 48, 32>>>(part, norm, temperature, mask, w_blend, probs);

    // 4) attn @ v -> transposed bf16 hi/lo
    attnv<<<dim3(NPIX / 128, NHEADS, BATCH), 128>>>(probs, qkv2, ah, al);

    // 5) proj 1x1 conv via HMMA (writes d_out)
    gemm_hmma<<<dim3(CDIM / 128, NPIX / 128, BATCH), 128, GEMM_SMEM>>>(
        wph, wpl, ah, al, out, (size_t)NPIX * CDIM, (size_t)CDIM * NPIX);

    // 6) fused pos path (slab), adds into d_out
    pos_slab<<<BATCH * CDIM * 8, 128>>>(qkv2, pos_w1, pos_w2, out);
}

// round 16
// speedup vs baseline: 1.1330x; 1.0989x over previous
#include <cuda_runtime.h>
#include <cuda_bf16.h>
#include <math.h>
#include <cstdint>

#define BATCH 4
#define CDIM 384
#define NHEADS 8
#define CPH 48
#define NPIX 16384
#define C3 1152

// ================= scratch =================
__device__ float g_qkv1[(size_t)BATCH * C3 * NPIX];
__device__ float g_qkv2[(size_t)BATCH * C3 * NPIX];
__device__ float g_normp[BATCH * 768 * 2];
__device__ float g_part[32 * 16 * 2304];
__device__ float g_probs[32 * 2304];
__device__ __nv_bfloat16 g_xT_hi[(size_t)BATCH * NPIX * CDIM];
__device__ __nv_bfloat16 g_xT_lo[(size_t)BATCH * NPIX * CDIM];
__device__ __nv_bfloat16 g_aT_hi[(size_t)BATCH * NPIX * CDIM];
__device__ __nv_bfloat16 g_aT_lo[(size_t)BATCH * NPIX * CDIM];
__device__ __nv_bfloat16 g_wq_hi[C3 * CDIM];
__device__ __nv_bfloat16 g_wq_lo[C3 * CDIM];
__device__ __nv_bfloat16 g_wp_hi[CDIM * CDIM];
__device__ __nv_bfloat16 g_wp_lo[CDIM * CDIM];

// ================= helpers =================
__device__ __forceinline__ uint32_t smem_u32(const void* p) {
    uint32_t a;
    asm("{ .reg .u64 t; cvta.to.shared.u64 t, %1; cvt.u32.u64 %0, t; }" : "=r"(a) : "l"(p));
    return a;
}
__device__ __forceinline__ void cp16(uint32_t s, const void* g) {
    asm volatile("cp.async.cg.shared.global [%0], [%1], 16;" :: "r"(s), "l"(g));
}
__device__ __forceinline__ void mma16816(float* c, const uint32_t* a, uint32_t b0, uint32_t b1) {
    asm volatile(
        "mma.sync.aligned.m16n8k16.row.col.f32.bf16.bf16.f32 "
        "{%0,%1,%2,%3}, {%4,%5,%6,%7}, {%8,%9}, {%0,%1,%2,%3};"
        : "+f"(c[0]), "+f"(c[1]), "+f"(c[2]), "+f"(c[3])
        : "r"(a[0]), "r"(a[1]), "r"(a[2]), "r"(a[3]), "r"(b0), "r"(b1));
}
__device__ __forceinline__ void ldsm4(uint32_t* r, uint32_t addr) {
    asm volatile("ldmatrix.sync.aligned.m8n8.x4.shared.b16 {%0,%1,%2,%3}, [%4];"
                 : "=r"(r[0]), "=r"(r[1]), "=r"(r[2]), "=r"(r[3]) : "r"(addr));
}

// ================= 3xBF16 HMMA GEMM: 128x128 CTA, 4 warps of 64x64, 2-stage =================
// R13/R15 proven schedule (do not touch).
#define AT 10240
#define STAGE (4 * AT)
#define GEMM_SMEM (2 * STAGE)

__global__ void __launch_bounds__(128, 2) gemm_hmma(
    const __nv_bfloat16* __restrict__ Ah, const __nv_bfloat16* __restrict__ Al,
    const __nv_bfloat16* __restrict__ Bh, const __nv_bfloat16* __restrict__ Bl,
    float* __restrict__ C, size_t strideB, size_t strideC) {
    extern __shared__ char sm[];
    const uint32_t sb = smem_u32(sm);
    const int tid = threadIdx.x;
    const int m0 = blockIdx.x * 128;
    const int n0 = blockIdx.y * 128;
    const __nv_bfloat16* bhp = Bh + blockIdx.z * strideB;
    const __nv_bfloat16* blp = Bl + blockIdx.z * strideB;
    float* Cp = C + blockIdx.z * strideC;

    const int wid = tid >> 5, lane = tid & 31;
    const int wm = (wid & 1) * 64, wn = (wid >> 1) * 64;
    const int qr = lane >> 2, qc = lane & 3;
    const int la = lane & 15, ha = lane >> 4;
    const int lb = (lane & 7) + (lane >> 4) * 8;
    const int mb = (lane >> 3) & 1;

    float acc[4][8][4];
#pragma unroll
    for (int i = 0; i < 4; i++)
#pragma unroll
        for (int j = 0; j < 8; j++)
#pragma unroll
            for (int t = 0; t < 4; t++) acc[i][j][t] = 0.f;

    const int r0 = tid >> 2;
    const int lc = (tid & 3) * 16;

    auto issue_half = [&](int k0, uint32_t bb, int p0) {
#pragma unroll
        for (int p = p0; p < p0 + 2; p++) {
            int row = r0 + p * 32;
            uint32_t so = (uint32_t)row * 80 + lc;
            cp16(bb + so, (const char*)(Ah + (size_t)(m0 + row) * 384 + k0) + lc);
            cp16(bb + AT + so, (const char*)(Al + (size_t)(m0 + row) * 384 + k0) + lc);
            cp16(bb + 2 * AT + so, (const char*)(bhp + (size_t)(n0 + row) * 384 + k0) + lc);
            cp16(bb + 3 * AT + so, (const char*)(blp + (size_t)(n0 + row) * 384 + k0) + lc);
        }
    };

    issue_half(0, sb, 0);
    issue_half(0, sb, 2);
    asm volatile("cp.async.commit_group;");

#pragma unroll 1
    for (int ch = 0; ch < 12; ch++) {
        asm volatile("cp.async.wait_group 0;");
        __syncthreads();

        const uint32_t bufb = sb + (ch & 1) * STAGE;
        const bool pf = ch < 11;
        const uint32_t nb = sb + ((ch + 1) & 1) * STAGE;
        const int k0n = (ch + 1) * 32;

        // ---- kc = 0 ----
        {
            uint32_t bh[4][4], bl[4][4];
#pragma unroll
            for (int jp = 0; jp < 4; jp++) {
                uint32_t br = (uint32_t)(wn + jp * 16 + lb) * 80 + (uint32_t)(mb * 8) * 2;
                ldsm4(bh[jp], bufb + 2 * AT + br);
                ldsm4(bl[jp], bufb + 3 * AT + br);
            }
            if (pf) issue_half(k0n, nb, 0);
#pragma unroll
            for (int mi = 0; mi < 4; mi++) {
                uint32_t ar = (uint32_t)(wm + mi * 16 + la) * 80 + (uint32_t)(ha * 8) * 2;
                uint32_t aH[4], aL[4];
                ldsm4(aH, bufb + ar);
                ldsm4(aL, bufb + AT + ar);
#pragma unroll
                for (int j = 0; j < 8; j++) {
                    uint32_t b0 = bh[j >> 1][(j & 1) * 2], b1 = bh[j >> 1][(j & 1) * 2 + 1];
                    uint32_t c0 = bl[j >> 1][(j & 1) * 2], c1 = bl[j >> 1][(j & 1) * 2 + 1];
                    mma16816(acc[mi][j], aH, b0, b1);
                    mma16816(acc[mi][j], aH, c0, c1);
                    mma16816(acc[mi][j], aL, b0, b1);
                }
            }
            if (pf) {
                issue_half(k0n, nb, 2);
                asm volatile("cp.async.commit_group;");
            }
        }
        // ---- kc = 16 ----
        {
            uint32_t bh[4][4], bl[4][4];
#pragma unroll
            for (int jp = 0; jp < 4; jp++) {
                uint32_t br = (uint32_t)(wn + jp * 16 + lb) * 80 + (uint32_t)(16 + mb * 8) * 2;
                ldsm4(bh[jp], bufb + 2 * AT + br);
                ldsm4(bl[jp], bufb + 3 * AT + br);
            }
#pragma unroll
            for (int mi = 0; mi < 4; mi++) {
                uint32_t ar = (uint32_t)(wm + mi * 16 + la) * 80 + (uint32_t)(16 + ha * 8) * 2;
                uint32_t aH[4], aL[4];
                ldsm4(aH, bufb + ar);
                ldsm4(aL, bufb + AT + ar);
#pragma unroll
                for (int j = 0; j < 8; j++) {
                    uint32_t b0 = bh[j >> 1][(j & 1) * 2], b1 = bh[j >> 1][(j & 1) * 2 + 1];
                    uint32_t c0 = bl[j >> 1][(j & 1) * 2], c1 = bl[j >> 1][(j & 1) * 2 + 1];
                    mma16816(acc[mi][j], aH, b0, b1);
                    mma16816(acc[mi][j], aH, c0, c1);
                    mma16816(acc[mi][j], aL, b0, b1);
                }
            }
        }
    }

#pragma unroll
    for (int mi = 0; mi < 4; mi++) {
        int rr = m0 + wm + mi * 16 + qr;
#pragma unroll
        for (int j = 0; j < 8; j++) {
            int cc = n0 + wn + j * 8 + qc * 2;
            float* cp = Cp + (size_t)rr * NPIX + cc;
            *(float2*)cp = make_float2(acc[mi][j][0], acc[mi][j][1]);
            *(float2*)(cp + (size_t)8 * NPIX) = make_float2(acc[mi][j][2], acc[mi][j][3]);
        }
    }
}

// ================= fp32 -> bf16 hi/lo converters =================
__global__ void cvt_split(const float* __restrict__ in, __nv_bfloat16* __restrict__ hi,
                          __nv_bfloat16* __restrict__ lo, int n) {
    int i = blockIdx.x * 256 + threadIdx.x;
    if (i >= n) return;
    float v = in[i];
    __nv_bfloat16 h = __float2bfloat16_rn(v);
    hi[i] = h;
    lo[i] = __float2bfloat16_rn(v - __bfloat162float(h));
}

// ================= transpose + split v2: 64x64 tiles, uint4 stores =================
__global__ void __launch_bounds__(256) transpose_split2(
    const float* __restrict__ x, __nv_bfloat16* __restrict__ th,
    __nv_bfloat16* __restrict__ tl) {
    __shared__ float ts[64][65];
    const int b = blockIdx.z;
    const int n0 = blockIdx.x * 64, c0 = blockIdx.y * 64;
    const int tid = threadIdx.x;
    for (int i = tid; i < 64 * 16; i += 256) {
        int c = i >> 4, s4 = (i & 15) * 4;
        float4 v = *(const float4*)(x + ((size_t)b * CDIM + c0 + c) * NPIX + n0 + s4);
        ts[c][s4] = v.x; ts[c][s4 + 1] = v.y; ts[c][s4 + 2] = v.z; ts[c][s4 + 3] = v.w;
    }
    __syncthreads();
    for (int i = tid; i < 1024; i += 256) {
        int buf = i >> 9, rem = i & 511, n = rem >> 3, g = rem & 7;
        uint32_t u[4];
#pragma unroll
        for (int jj = 0; jj < 4; jj++) {
            float v0 = ts[g * 8 + jj * 2][n], v1 = ts[g * 8 + jj * 2 + 1][n];
            __nv_bfloat16 h0 = __float2bfloat16_rn(v0);
            __nv_bfloat16 h1 = __float2bfloat16_rn(v1);
            if (buf) {
                h0 = __float2bfloat16_rn(v0 - __bfloat162float(h0));
                h1 = __float2bfloat16_rn(v1 - __bfloat162float(h1));
            }
            u[jj] = (uint32_t)__bfloat16_as_ushort(h0) |
                    ((uint32_t)__bfloat16_as_ushort(h1) << 16);
        }
        __nv_bfloat16* base = buf ? tl : th;
        *(uint4*)(base + ((size_t)b * NPIX + n0 + n) * CDIM + c0 + g * 8) =
            make_uint4(u[0], u[1], u[2], u[3]);
    }
}

// ================= half-channel dwconv 3x3 + norm partials (deterministic) =================
// One block per (b, ch, half). 66 rows (incl. zero-staged halo) in 33.8KB smem -> 6 CTAs/SM.
__global__ void __launch_bounds__(256) dwconv_half(
    const float* __restrict__ in, const float* __restrict__ w,
    float* __restrict__ out, float* __restrict__ normp) {
    extern __shared__ float img[];  // 66 * 128 floats
    const int blk = blockIdx.x;
    const int half = blk & 1;
    const int ch = (blk >> 1) % C3;
    const int b = blk / (2 * C3);
    const int y0 = half * 64;
    const int tid = threadIdx.x;
    const float* ip = in + ((size_t)b * C3 + ch) * NPIX;

    for (int i = tid; i < 66 * 32; i += 256) {
        int r = i >> 5, c4 = (i & 31) * 4;
        int y = y0 - 1 + r;
        float4 v = (y >= 0 && y <= 127) ? *(const float4*)(ip + y * 128 + c4)
                                        : make_float4(0.f, 0.f, 0.f, 0.f);
        *(float4*)&img[r * 128 + c4] = v;
    }
    __syncthreads();
    const float* wp = w + ch * 9;
    float w00 = wp[0], w01 = wp[1], w02 = wp[2];
    float w10 = wp[3], w11 = wp[4], w12 = wp[5];
    float w20 = wp[6], w21 = wp[7], w22 = wp[8];
    float* op = out + ((size_t)b * C3 + ch) * NPIX;
    float ss = 0.f;
    for (int i = tid; i < 64 * 32; i += 256) {
        int x4 = (i & 31) * 4, j = i >> 5;
        float o0 = 0.f, o1 = 0.f, o2 = 0.f, o3 = 0.f;
#pragma unroll
        for (int ky = 0; ky < 3; ky++) {
            const float* rp = img + (j + ky) * 128;  // halo rows zero-staged
            float4 c = *(const float4*)(rp + x4);
            float lft = (x4 > 0) ? rp[x4 - 1] : 0.f;
            float rgt = (x4 < 124) ? rp[x4 + 4] : 0.f;
            float wa = (ky == 0) ? w00 : (ky == 1) ? w10 : w20;
            float wb = (ky == 0) ? w01 : (ky == 1) ? w11 : w21;
            float wc = (ky == 0) ? w02 : (ky == 1) ? w12 : w22;
            o0 += wa * lft + wb * c.x + wc * c.y;
            o1 += wa * c.x + wb * c.y + wc * c.z;
            o2 += wa * c.y + wb * c.z + wc * c.w;
            o3 += wa * c.z + wb * c.w + wc * rgt;
        }
        *(float4*)(op + (y0 + j) * 128 + x4) = make_float4(o0, o1, o2, o3);
        ss += o0 * o0 + o1 * o1 + o2 * o2 + o3 * o3;
    }
    if (ch < 768) {
        __shared__ float red[8];
#pragma unroll
        for (int o = 16; o; o >>= 1) ss += __shfl_down_sync(~0u, ss, o);
        if ((tid & 31) == 0) red[tid >> 5] = ss;
        __syncthreads();
        if (tid < 8) {
            ss = red[tid];
#pragma unroll
            for (int o = 4; o; o >>= 1) ss += __shfl_down_sync(0xffu, ss, o);
            if (tid == 0) normp[(b * 768 + ch) * 2 + half] = ss;
        }
    }
}

// ================= fused pos path per 16-row slab =================
__global__ void __launch_bounds__(128) pos_slab(
    const float* __restrict__ v, const float* __restrict__ w1,
    const float* __restrict__ w2, float* __restrict__ out) {
    __shared__ float inb[20][128];
    __shared__ float mid[18][132];
    const int blk = blockIdx.x;
    const int s = blk & 7;
    const int ch = (blk >> 3) % CDIM;
    const int b = blk / (CDIM * 8);
    const int y0 = s * 16;
    const int tid = threadIdx.x;
    const float* ip = v + ((size_t)b * C3 + 768 + ch) * NPIX;

    for (int i = tid; i < 20 * 32; i += 128) {
        int r = i >> 5, c4 = (i & 31) * 4;
        int y = y0 - 2 + r;
        float4 val = (y >= 0 && y <= 127) ? *(const float4*)(ip + y * 128 + c4)
                                          : make_float4(0.f, 0.f, 0.f, 0.f);
        *(float4*)&inb[r][c4] = val;
    }
    __syncthreads();

    {
        const float* wp = w1 + ch * 9;
        float w00 = wp[0], w01 = wp[1], w02 = wp[2];
        float w10 = wp[3], w11 = wp[4], w12 = wp[5];
        float w20 = wp[6], w21 = wp[7], w22 = wp[8];
        for (int i = tid; i < 18 * 32; i += 128) {
            int r = i >> 5, c4 = (i & 31) * 4;
            int m = y0 - 1 + r;
            float o0 = 0.f, o1 = 0.f, o2 = 0.f, o3 = 0.f;
            if (m >= 0 && m <= 127) {
#pragma unroll
                for (int ky = 0; ky < 3; ky++) {
                    int yy = m + ky - 1;
                    if (yy < 0 || yy > 127) continue;
                    const float* rp = inb[r + ky];
                    float4 c = *(const float4*)(rp + c4);
                    float lft = (c4 > 0) ? rp[c4 - 1] : 0.f;
                    float rgt = (c4 < 124) ? rp[c4 + 4] : 0.f;
                    float wa = (ky == 0) ? w00 : (ky == 1) ? w10 : w20;
                    float wb = (ky == 0) ? w01 : (ky == 1) ? w11 : w21;
                    float wc = (ky == 0) ? w02 : (ky == 1) ? w12 : w22;
                    o0 += wa * lft + wb * c.x + wc * c.y;
                    o1 += wa * c.x + wb * c.y + wc * c.z;
                    o2 += wa * c.y + wb * c.z + wc * c.w;
                    o3 += wa * c.z + wb * c.w + wc * rgt;
                }
                o0 = 0.5f * o0 * (1.0f + erff(o0 * 0.70710678118654752f));
                o1 = 0.5f * o1 * (1.0f + erff(o1 * 0.70710678118654752f));
                o2 = 0.5f * o2 * (1.0f + erff(o2 * 0.70710678118654752f));
                o3 = 0.5f * o3 * (1.0f + erff(o3 * 0.70710678118654752f));
            }
            mid[r][c4] = o0; mid[r][c4 + 1] = o1;
            mid[r][c4 + 2] = o2; mid[r][c4 + 3] = o3;
        }
    }
    __syncthreads();

    {
        const float* wp = w2 + ch * 9;
        float w00 = wp[0], w01 = wp[1], w02 = wp[2];
        float w10 = wp[3], w11 = wp[4], w12 = wp[5];
        float w20 = wp[6], w21 = wp[7], w22 = wp[8];
        float* op = out + ((size_t)b * CDIM + ch) * NPIX;
        for (int i = tid; i < 16 * 32; i += 128) {
            int j = i >> 5, c4 = (i & 31) * 4;
            int y = y0 + j;
            float o0 = 0.f, o1 = 0.f, o2 = 0.f, o3 = 0.f;
#pragma unroll
            for (int ky = 0; ky < 3; ky++) {
                const float* rp = mid[j + ky];
                float c0 = rp[c4], c1 = rp[c4 + 1], c2 = rp[c4 + 2], c3 = rp[c4 + 3];
                float lft = (c4 > 0) ? rp[c4 - 1] : 0.f;
                float rgt = (c4 < 124) ? rp[c4 + 4] : 0.f;
                float wa = (ky == 0) ? w00 : (ky == 1) ? w10 : w20;
                float wb = (ky == 0) ? w01 : (ky == 1) ? w11 : w21;
                float wc = (ky == 0) ? w02 : (ky == 1) ? w12 : w22;
                o0 += wa * lft + wb * c0 + wc * c1;
                o1 += wa * c0 + wb * c1 + wc * c2;
                o2 += wa * c1 + wb * c2 + wc * c3;
                o3 += wa * c2 + wb * c3 + wc * rgt;
            }
            float4 prev = *(const float4*)(op + y * 128 + c4);
            *(float4*)(op + y * 128 + c4) =
                make_float4(prev.x + o0, prev.y + o1, prev.z + o2, prev.w + o3);
        }
    }
}

// ================= q.k^T partials =================
__global__ void attn_partial(const float* __restrict__ qkv, float* __restrict__ part) {
    __shared__ float qs[48][68];
    __shared__ float ks[48][68];
    const int split = blockIdx.x, h = blockIdx.y, b = blockIdx.z;
    const int tid = threadIdx.x;
    const float* qbase = qkv + ((size_t)b * C3 + h * CPH) * NPIX;
    const float* kbase = qkv + ((size_t)b * C3 + 384 + h * CPH) * NPIX;
    const int tx = tid & 15, ty = tid >> 4;
    const int c0 = ty * 3, d0 = tx * 3;
    float acc[3][3];
#pragma unroll
    for (int i = 0; i < 3; i++)
#pragma unroll
        for (int j = 0; j < 3; j++) acc[i][j] = 0.f;

    for (int chunk = 0; chunk < 16; chunk++) {
        int n0 = split * 1024 + chunk * 64;
        __syncthreads();
#pragma unroll
        for (int r = 0; r < 3; r++) {
            int v = tid + r * 256;
            int row = v >> 4;
            int col = (v & 15) << 2;
            *(float4*)&qs[row][col] = *(const float4*)(qbase + (size_t)row * NPIX + n0 + col);
            *(float4*)&ks[row][col] = *(const float4*)(kbase + (size_t)row * NPIX + n0 + col);
        }
        __syncthreads();
#pragma unroll
        for (int i = 0; i < 64; i += 4) {
            float4 q0 = *(const float4*)&qs[c0][i];
            float4 q1 = *(const float4*)&qs[c0 + 1][i];
            float4 q2 = *(const float4*)&qs[c0 + 2][i];
            float4 k0 = *(const float4*)&ks[d0][i];
            float4 k1 = *(const float4*)&ks[d0 + 1][i];
            float4 k2 = *(const float4*)&ks[d0 + 2][i];
            acc[0][0] += q0.x * k0.x + q0.y * k0.y + q0.z * k0.z + q0.w * k0.w;
            acc[0][1] += q0.x * k1.x + q0.y * k1.y + q0.z * k1.z + q0.w * k1.w;
            acc[0][2] += q0.x * k2.x + q0.y * k2.y + q0.z * k2.z + q0.w * k2.w;
            acc[1][0] += q1.x * k0.x + q1.y * k0.y + q1.z * k0.z + q1.w * k0.w;
            acc[1][1] += q1.x * k1.x + q1.y * k1.y + q1.z * k1.z + q1.w * k1.w;
            acc[1][2] += q1.x * k2.x + q1.y * k2.y + q1.z * k2.z + q1.w * k2.w;
            acc[2][0] += q2.x * k0.x + q2.y * k0.y + q2.z * k0.z + q2.w * k0.w;
            acc[2][1] += q2.x * k1.x + q2.y * k1.y + q2.z * k1.z + q2.w * k1.w;
            acc[2][2] += q2.x * k2.x + q2.y * k2.y + q2.z * k2.z + q2.w * k2.w;
        }
    }
    float* pp = part + ((size_t)((b * NHEADS + h) * 16 + split)) * 2304;
#pragma unroll
    for (int i = 0; i < 3; i++)
#pragma unroll
        for (int j = 0; j < 3; j++) pp[(c0 + i) * 48 + d0 + j] = acc[i][j];
}

// ================= fused: reduce partials -> logits -> dual softmax blend =================
__global__ void attn_finish(const float* __restrict__ part, const float* __restrict__ normp,
                            const float* __restrict__ temp, const int* __restrict__ mask,
                            const float* __restrict__ wb, float* __restrict__ probs) {
    int row = blockIdx.x;
    int c = row % 48;
    int h = (row / 48) % NHEADS;
    int b = row / (48 * NHEADS);
    int bh = b * NHEADS + h;
    int lane = threadIdx.x;
    const int* mp = mask + (h * 48 + c) * 48;
    int qidx = b * 768 + h * CPH + c;
    float inq = 1.0f / fmaxf(sqrtf(normp[qidx * 2] + normp[qidx * 2 + 1]), 1e-12f);
    float tmp = temp[h];

    float lg[2];
#pragma unroll
    for (int t = 0; t < 2; t++) {
        int d = lane + t * 32;
        if (d < 48) {
            float s = 0.f;
#pragma unroll
            for (int sp = 0; sp < 16; sp++)
                s += part[((size_t)(bh * 16 + sp)) * 2304 + c * 48 + d];
            int kidx = b * 768 + 384 + h * CPH + d;
            float ink = 1.0f / fmaxf(sqrtf(normp[kidx * 2] + normp[kidx * 2 + 1]), 1e-12f);
            lg[t] = s * inq * ink * tmp;
        } else {
            lg[t] = -INFINITY;
        }
    }
    bool v1ok = lane + 32 < 48;
    float a0 = lg[0], a1 = lg[1];
    float b0 = (mp[lane] == 0) ? -1e9f : a0;
    float b1 = v1ok ? ((mp[lane + 32] == 0) ? -1e9f : a1) : -INFINITY;
    float mA = fmaxf(a0, a1), mB = fmaxf(b0, b1);
#pragma unroll
    for (int o = 16; o; o >>= 1) {
        mA = fmaxf(mA, __shfl_xor_sync(~0u, mA, o));
        mB = fmaxf(mB, __shfl_xor_sync(~0u, mB, o));
    }
    float eA0 = expf(a0 - mA);
    float eA1 = v1ok ? expf(a1 - mA) : 0.f;
    float eB0 = expf(b0 - mB);
    float eB1 = v1ok ? expf(b1 - mB) : 0.f;
    float sA = eA0 + eA1, sB = eB0 + eB1;
#pragma unroll
    for (int o = 16; o; o >>= 1) {
        sA += __shfl_xor_sync(~0u, sA, o);
        sB += __shfl_xor_sync(~0u, sB, o);
    }
    float w0 = wb[0], w1 = wb[1];
    float wm = fmaxf(w0, w1);
    float ew0 = expf(w0 - wm), ew1 = expf(w1 - wm);
    float wsum = ew0 + ew1;
    float blend0 = ew0 / wsum, blend1 = ew1 / wsum;
    float* pp = probs + (size_t)row * 48;
    pp[lane] = blend0 * eA0 / sA + blend1 * eB0 / sB;
    if (v1ok) pp[lane + 32] = blend0 * eA1 / sA + blend1 * eB1 / sB;
}

// ================= out = attn @ v -> transposed bf16 hi/lo (coalesced) =================
__global__ void attnv(const float* __restrict__ probs, const float* __restrict__ qkv2,
                      __nv_bfloat16* __restrict__ th, __nv_bfloat16* __restrict__ tl) {
    __shared__ float a_s[2304];
    __shared__ uint32_t sh[2][128][26];
    const int h = blockIdx.y, b = blockIdx.z;
    const int tid = threadIdx.x;
    const int n0 = blockIdx.x * 128;
    const int n = n0 + tid;
    const float* ap = probs + (size_t)(b * NHEADS + h) * 2304;
    for (int i = tid; i < 2304; i += 128) a_s[i] = ap[i];
    __syncthreads();
    const float* vbase = qkv2 + ((size_t)b * C3 + 768 + h * CPH) * NPIX + n;
    float vr[48];
#pragma unroll
    for (int d = 0; d < 48; d++) vr[d] = vbase[(size_t)d * NPIX];
    float accv[48];
#pragma unroll 4
    for (int c = 0; c < 48; c++) {
        float acc = 0.f;
#pragma unroll
        for (int d = 0; d < 48; d++) acc += a_s[c * 48 + d] * vr[d];
        accv[c] = acc;
    }
#pragma unroll
    for (int c2 = 0; c2 < 24; c2++) {
        float v0 = accv[2 * c2], v1 = accv[2 * c2 + 1];
        __nv_bfloat16 h0 = __float2bfloat16_rn(v0);
        __nv_bfloat16 h1 = __float2bfloat16_rn(v1);
        __nv_bfloat16 l0 = __float2bfloat16_rn(v0 - __bfloat162float(h0));
        __nv_bfloat16 l1 = __float2bfloat16_rn(v1 - __bfloat162float(h1));
        sh[0][tid][c2] = (uint32_t)__bfloat16_as_ushort(h0) |
                         ((uint32_t)__bfloat16_as_ushort(h1) << 16);
        sh[1][tid][c2] = (uint32_t)__bfloat16_as_ushort(l0) |
                         ((uint32_t)__bfloat16_as_ushort(l1) << 16);
    }
    __syncthreads();
    for (int idx = tid; idx < 2 * 128 * 12; idx += 128) {
        int a = idx / (128 * 12);
        int r = (idx / 12) & 127;
        int j = idx % 12;
        uint2 v = *(const uint2*)&sh[a][r][j * 2];
        __nv_bfloat16* base = a ? tl : th;
        *((uint2*)(base + ((size_t)b * NPIX + n0 + r) * CDIM + h * CPH) + j) = v;
    }
}

// ================= launch =================
extern "C" void kernel_launch(void* const* d_in, const int* in_sizes, int n_in,
                              void* d_out, int out_size) {
    const float* x           = (const float*)d_in[0];
    const int*   mask        = (const int*)d_in[1];
    const float* qkv_w       = (const float*)d_in[2];
    const float* dw_w        = (const float*)d_in[3];
    const float* proj_w      = (const float*)d_in[4];
    const float* temperature = (const float*)d_in[5];
    const float* w_blend     = (const float*)d_in[6];
    const float* pos_w1      = (const float*)d_in[7];
    const float* pos_w2      = (const float*)d_in[8];
    float* out = (float*)d_out;

    float *qkv1, *qkv2, *normp, *part, *probs;
    __nv_bfloat16 *xh, *xl, *ah, *al, *wqh, *wql, *wph, *wpl;
    cudaGetSymbolAddress((void**)&qkv1, g_qkv1);
    cudaGetSymbolAddress((void**)&qkv2, g_qkv2);
    cudaGetSymbolAddress((void**)&normp, g_normp);
    cudaGetSymbolAddress((void**)&part, g_part);
    cudaGetSymbolAddress((void**)&probs, g_probs);
    cudaGetSymbolAddress((void**)&xh, g_xT_hi);
    cudaGetSymbolAddress((void**)&xl, g_xT_lo);
    cudaGetSymbolAddress((void**)&ah, g_aT_hi);
    cudaGetSymbolAddress((void**)&al, g_aT_lo);
    cudaGetSymbolAddress((void**)&wqh, g_wq_hi);
    cudaGetSymbolAddress((void**)&wql, g_wq_lo);
    cudaGetSymbolAddress((void**)&wph, g_wp_hi);
    cudaGetSymbolAddress((void**)&wpl, g_wp_lo);

    static bool init_done = false;
    if (!init_done) {
        cudaFuncSetAttribute(gemm_hmma, cudaFuncAttributeMaxDynamicSharedMemorySize, GEMM_SMEM);
        cudaFuncSetAttribute(dwconv_half, cudaFuncAttributeMaxDynamicSharedMemorySize, 66 * 128 * 4);
        init_done = true;
    }

    // 0) operand conversion
    cvt_split<<<(C3 * CDIM + 255) / 256, 256>>>(qkv_w, wqh, wql, C3 * CDIM);
    cvt_split<<<(CDIM * CDIM + 255) / 256, 256>>>(proj_w, wph, wpl, CDIM * CDIM);
    transpose_split2<<<dim3(NPIX / 64, CDIM / 64, BATCH), 256>>>(x, xh, xl);

    // 1) qkv 1x1 conv via HMMA
    gemm_hmma<<<dim3(C3 / 128, NPIX / 128, BATCH), 128, GEMM_SMEM>>>(
        wqh, wql, xh, xl, qkv1, (size_t)NPIX * CDIM, (size_t)C3 * NPIX);

    // 2) depthwise 3x3 (half-channel) + norm partials
    dwconv_half<<<BATCH * C3 * 2, 256, 66 * 128 * 4>>>(qkv1, dw_w, qkv2, normp);

    // 3) q.k^T partials, then fused reduce + dual softmax
    attn_partial<<<dim3(16, NHEADS, BATCH), 256>>>(qkv2, part);
    attn_finish<<<BATCH * NHEADS * 48, 32>>>(part, normp, temperature, mask, w_blend, probs);

    // 4) attn @ v -> transposed bf16 hi/lo
    attnv<<<dim3(NPIX / 128, NHEADS, BATCH), 128>>>(probs, qkv2, ah, al);

    // 5) proj 1x1 conv via HMMA (writes d_out)
    gemm_hmma<<<dim3(CDIM / 128, NPIX / 128, BATCH), 128, GEMM_SMEM>>>(
        wph, wpl, ah, al, out, (size_t)NPIX * CDIM, (size_t)CDIM * NPIX);

    // 6) fused pos path (slab), adds into d_out
    pos_slab<<<BATCH * CDIM * 8, 128>>>(qkv2, pos_w1, pos_w2, out);
}

// round 17
// speedup vs baseline: 1.1710x; 1.0335x over previous
#include <cuda_runtime.h>
#include <cuda_bf16.h>
#include <cuda_fp16.h>
#include <math.h>
#include <cstdint>

#define BATCH 4
#define CDIM 384
#define NHEADS 8
#define CPH 48
#define NPIX 16384
#define C3 1152

// ================= scratch =================
__device__ __half g_qkv1h[(size_t)BATCH * C3 * NPIX];
__device__ float g_qkv2[(size_t)BATCH * C3 * NPIX];
__device__ float g_normp[BATCH * 768 * 2];
__device__ float g_part[32 * 32 * 2304];
__device__ float g_probs[32 * 2304];
__device__ __nv_bfloat16 g_xT_hi[(size_t)BATCH * NPIX * CDIM];
__device__ __nv_bfloat16 g_xT_lo[(size_t)BATCH * NPIX * CDIM];
__device__ __nv_bfloat16 g_aT_hi[(size_t)BATCH * NPIX * CDIM];
__device__ __nv_bfloat16 g_aT_lo[(size_t)BATCH * NPIX * CDIM];
__device__ __nv_bfloat16 g_wq_hi[C3 * CDIM];
__device__ __nv_bfloat16 g_wq_lo[C3 * CDIM];
__device__ __nv_bfloat16 g_wp_hi[CDIM * CDIM];
__device__ __nv_bfloat16 g_wp_lo[CDIM * CDIM];

// ================= helpers =================
__device__ __forceinline__ uint32_t smem_u32(const void* p) {
    uint32_t a;
    asm("{ .reg .u64 t; cvta.to.shared.u64 t, %1; cvt.u32.u64 %0, t; }" : "=r"(a) : "l"(p));
    return a;
}
__device__ __forceinline__ void cp16(uint32_t s, const void* g) {
    asm volatile("cp.async.cg.shared.global [%0], [%1], 16;" :: "r"(s), "l"(g));
}
__device__ __forceinline__ void mma16816(float* c, const uint32_t* a, uint32_t b0, uint32_t b1) {
    asm volatile(
        "mma.sync.aligned.m16n8k16.row.col.f32.bf16.bf16.f32 "
        "{%0,%1,%2,%3}, {%4,%5,%6,%7}, {%8,%9}, {%0,%1,%2,%3};"
        : "+f"(c[0]), "+f"(c[1]), "+f"(c[2]), "+f"(c[3])
        : "r"(a[0]), "r"(a[1]), "r"(a[2]), "r"(a[3]), "r"(b0), "r"(b1));
}
__device__ __forceinline__ void ldsm4(uint32_t* r, uint32_t addr) {
    asm volatile("ldmatrix.sync.aligned.m8n8.x4.shared.b16 {%0,%1,%2,%3}, [%4];"
                 : "=r"(r[0]), "=r"(r[1]), "=r"(r[2]), "=r"(r[3]) : "r"(addr));
}

// ================= 3xBF16 HMMA GEMM: 128x128 CTA, 4 warps of 64x64, 2-stage =================
// R13/R15 proven schedule; epilogue templated on output type (float or __half).
#define AT 10240
#define STAGE (4 * AT)
#define GEMM_SMEM (2 * STAGE)

template <typename OutT>
__global__ void __launch_bounds__(128, 2) gemm_hmma(
    const __nv_bfloat16* __restrict__ Ah, const __nv_bfloat16* __restrict__ Al,
    const __nv_bfloat16* __restrict__ Bh, const __nv_bfloat16* __restrict__ Bl,
    OutT* __restrict__ C, size_t strideB, size_t strideC) {
    extern __shared__ char sm[];
    const uint32_t sb = smem_u32(sm);
    const int tid = threadIdx.x;
    const int m0 = blockIdx.x * 128;
    const int n0 = blockIdx.y * 128;
    const __nv_bfloat16* bhp = Bh + blockIdx.z * strideB;
    const __nv_bfloat16* blp = Bl + blockIdx.z * strideB;
    OutT* Cp = C + blockIdx.z * strideC;

    const int wid = tid >> 5, lane = tid & 31;
    const int wm = (wid & 1) * 64, wn = (wid >> 1) * 64;
    const int qr = lane >> 2, qc = lane & 3;
    const int la = lane & 15, ha = lane >> 4;
    const int lb = (lane & 7) + (lane >> 4) * 8;
    const int mb = (lane >> 3) & 1;

    float acc[4][8][4];
#pragma unroll
    for (int i = 0; i < 4; i++)
#pragma unroll
        for (int j = 0; j < 8; j++)
#pragma unroll
            for (int t = 0; t < 4; t++) acc[i][j][t] = 0.f;

    const int r0 = tid >> 2;
    const int lc = (tid & 3) * 16;

    auto issue_half = [&](int k0, uint32_t bb, int p0) {
#pragma unroll
        for (int p = p0; p < p0 + 2; p++) {
            int row = r0 + p * 32;
            uint32_t so = (uint32_t)row * 80 + lc;
            cp16(bb + so, (const char*)(Ah + (size_t)(m0 + row) * 384 + k0) + lc);
            cp16(bb + AT + so, (const char*)(Al + (size_t)(m0 + row) * 384 + k0) + lc);
            cp16(bb + 2 * AT + so, (const char*)(bhp + (size_t)(n0 + row) * 384 + k0) + lc);
            cp16(bb + 3 * AT + so, (const char*)(blp + (size_t)(n0 + row) * 384 + k0) + lc);
        }
    };

    issue_half(0, sb, 0);
    issue_half(0, sb, 2);
    asm volatile("cp.async.commit_group;");

#pragma unroll 1
    for (int ch = 0; ch < 12; ch++) {
        asm volatile("cp.async.wait_group 0;");
        __syncthreads();

        const uint32_t bufb = sb + (ch & 1) * STAGE;
        const bool pf = ch < 11;
        const uint32_t nb = sb + ((ch + 1) & 1) * STAGE;
        const int k0n = (ch + 1) * 32;

        // ---- kc = 0 ----
        {
            uint32_t bh[4][4], bl[4][4];
#pragma unroll
            for (int jp = 0; jp < 4; jp++) {
                uint32_t br = (uint32_t)(wn + jp * 16 + lb) * 80 + (uint32_t)(mb * 8) * 2;
                ldsm4(bh[jp], bufb + 2 * AT + br);
                ldsm4(bl[jp], bufb + 3 * AT + br);
            }
            if (pf) issue_half(k0n, nb, 0);
#pragma unroll
            for (int mi = 0; mi < 4; mi++) {
                uint32_t ar = (uint32_t)(wm + mi * 16 + la) * 80 + (uint32_t)(ha * 8) * 2;
                uint32_t aH[4], aL[4];
                ldsm4(aH, bufb + ar);
                ldsm4(aL, bufb + AT + ar);
#pragma unroll
                for (int j = 0; j < 8; j++) {
                    uint32_t b0 = bh[j >> 1][(j & 1) * 2], b1 = bh[j >> 1][(j & 1) * 2 + 1];
                    uint32_t c0 = bl[j >> 1][(j & 1) * 2], c1 = bl[j >> 1][(j & 1) * 2 + 1];
                    mma16816(acc[mi][j], aH, b0, b1);
                    mma16816(acc[mi][j], aH, c0, c1);
                    mma16816(acc[mi][j], aL, b0, b1);
                }
            }
            if (pf) {
                issue_half(k0n, nb, 2);
                asm volatile("cp.async.commit_group;");
            }
        }
        // ---- kc = 16 ----
        {
            uint32_t bh[4][4], bl[4][4];
#pragma unroll
            for (int jp = 0; jp < 4; jp++) {
                uint32_t br = (uint32_t)(wn + jp * 16 + lb) * 80 + (uint32_t)(16 + mb * 8) * 2;
                ldsm4(bh[jp], bufb + 2 * AT + br);
                ldsm4(bl[jp], bufb + 3 * AT + br);
            }
#pragma unroll
            for (int mi = 0; mi < 4; mi++) {
                uint32_t ar = (uint32_t)(wm + mi * 16 + la) * 80 + (uint32_t)(16 + ha * 8) * 2;
                uint32_t aH[4], aL[4];
                ldsm4(aH, bufb + ar);
                ldsm4(aL, bufb + AT + ar);
#pragma unroll
                for (int j = 0; j < 8; j++) {
                    uint32_t b0 = bh[j >> 1][(j & 1) * 2], b1 = bh[j >> 1][(j & 1) * 2 + 1];
                    uint32_t c0 = bl[j >> 1][(j & 1) * 2], c1 = bl[j >> 1][(j & 1) * 2 + 1];
                    mma16816(acc[mi][j], aH, b0, b1);
                    mma16816(acc[mi][j], aH, c0, c1);
                    mma16816(acc[mi][j], aL, b0, b1);
                }
            }
        }
    }

#pragma unroll
    for (int mi = 0; mi < 4; mi++) {
        int rr = m0 + wm + mi * 16 + qr;
#pragma unroll
        for (int j = 0; j < 8; j++) {
            int cc = n0 + wn + j * 8 + qc * 2;
            OutT* cp = Cp + (size_t)rr * NPIX + cc;
            if constexpr (sizeof(OutT) == 4) {
                *(float2*)cp = make_float2(acc[mi][j][0], acc[mi][j][1]);
                *(float2*)(cp + (size_t)8 * NPIX) = make_float2(acc[mi][j][2], acc[mi][j][3]);
            } else {
                *(__half2*)cp = __floats2half2_rn(acc[mi][j][0], acc[mi][j][1]);
                *(__half2*)(cp + (size_t)8 * NPIX) =
                    __floats2half2_rn(acc[mi][j][2], acc[mi][j][3]);
            }
        }
    }
}

// ================= fp32 -> bf16 hi/lo converters =================
__global__ void cvt_split(const float* __restrict__ in, __nv_bfloat16* __restrict__ hi,
                          __nv_bfloat16* __restrict__ lo, int n) {
    int i = blockIdx.x * 256 + threadIdx.x;
    if (i >= n) return;
    float v = in[i];
    __nv_bfloat16 h = __float2bfloat16_rn(v);
    hi[i] = h;
    lo[i] = __float2bfloat16_rn(v - __bfloat162float(h));
}

// ================= transpose + split v2: 64x64 tiles, uint4 stores =================
__global__ void __launch_bounds__(256) transpose_split2(
    const float* __restrict__ x, __nv_bfloat16* __restrict__ th,
    __nv_bfloat16* __restrict__ tl) {
    __shared__ float ts[64][65];
    const int b = blockIdx.z;
    const int n0 = blockIdx.x * 64, c0 = blockIdx.y * 64;
    const int tid = threadIdx.x;
    for (int i = tid; i < 64 * 16; i += 256) {
        int c = i >> 4, s4 = (i & 15) * 4;
        float4 v = *(const float4*)(x + ((size_t)b * CDIM + c0 + c) * NPIX + n0 + s4);
        ts[c][s4] = v.x; ts[c][s4 + 1] = v.y; ts[c][s4 + 2] = v.z; ts[c][s4 + 3] = v.w;
    }
    __syncthreads();
    for (int i = tid; i < 1024; i += 256) {
        int buf = i >> 9, rem = i & 511, n = rem >> 3, g = rem & 7;
        uint32_t u[4];
#pragma unroll
        for (int jj = 0; jj < 4; jj++) {
            float v0 = ts[g * 8 + jj * 2][n], v1 = ts[g * 8 + jj * 2 + 1][n];
            __nv_bfloat16 h0 = __float2bfloat16_rn(v0);
            __nv_bfloat16 h1 = __float2bfloat16_rn(v1);
            if (buf) {
                h0 = __float2bfloat16_rn(v0 - __bfloat162float(h0));
                h1 = __float2bfloat16_rn(v1 - __bfloat162float(h1));
            }
            u[jj] = (uint32_t)__bfloat16_as_ushort(h0) |
                    ((uint32_t)__bfloat16_as_ushort(h1) << 16);
        }
        __nv_bfloat16* base = buf ? tl : th;
        *(uint4*)(base + ((size_t)b * NPIX + n0 + n) * CDIM + c0 + g * 8) =
            make_uint4(u[0], u[1], u[2], u[3]);
    }
}

// ================= half-channel dwconv 3x3 (fp16 in, fp32 out) + norm partials =================
__global__ void __launch_bounds__(256) dwconv_half(
    const __half* __restrict__ in, const float* __restrict__ w,
    float* __restrict__ out, float* __restrict__ normp) {
    extern __shared__ float img[];  // 66 * 128 floats
    const int blk = blockIdx.x;
    const int half = blk & 1;
    const int ch = (blk >> 1) % C3;
    const int b = blk / (2 * C3);
    const int y0 = half * 64;
    const int tid = threadIdx.x;
    const __half* ip = in + ((size_t)b * C3 + ch) * NPIX;

    for (int i = tid; i < 66 * 32; i += 256) {
        int r = i >> 5, c4 = (i & 31) * 4;
        int y = y0 - 1 + r;
        float4 v;
        if (y >= 0 && y <= 127) {
            uint2 raw = *(const uint2*)(ip + y * 128 + c4);
            float2 fa = __half22float2(*(__half2*)&raw.x);
            float2 fb = __half22float2(*(__half2*)&raw.y);
            v = make_float4(fa.x, fa.y, fb.x, fb.y);
        } else {
            v = make_float4(0.f, 0.f, 0.f, 0.f);
        }
        *(float4*)&img[r * 128 + c4] = v;
    }
    __syncthreads();
    const float* wp = w + ch * 9;
    float w00 = wp[0], w01 = wp[1], w02 = wp[2];
    float w10 = wp[3], w11 = wp[4], w12 = wp[5];
    float w20 = wp[6], w21 = wp[7], w22 = wp[8];
    float* op = out + ((size_t)b * C3 + ch) * NPIX;
    float ss = 0.f;
    for (int i = tid; i < 64 * 32; i += 256) {
        int x4 = (i & 31) * 4, j = i >> 5;
        float o0 = 0.f, o1 = 0.f, o2 = 0.f, o3 = 0.f;
#pragma unroll
        for (int ky = 0; ky < 3; ky++) {
            const float* rp = img + (j + ky) * 128;
            float4 c = *(const float4*)(rp + x4);
            float lft = (x4 > 0) ? rp[x4 - 1] : 0.f;
            float rgt = (x4 < 124) ? rp[x4 + 4] : 0.f;
            float wa = (ky == 0) ? w00 : (ky == 1) ? w10 : w20;
            float wb = (ky == 0) ? w01 : (ky == 1) ? w11 : w21;
            float wc = (ky == 0) ? w02 : (ky == 1) ? w12 : w22;
            o0 += wa * lft + wb * c.x + wc * c.y;
            o1 += wa * c.x + wb * c.y + wc * c.z;
            o2 += wa * c.y + wb * c.z + wc * c.w;
            o3 += wa * c.z + wb * c.w + wc * rgt;
        }
        *(float4*)(op + (y0 + j) * 128 + x4) = make_float4(o0, o1, o2, o3);
        ss += o0 * o0 + o1 * o1 + o2 * o2 + o3 * o3;
    }
    if (ch < 768) {
        __shared__ float red[8];
#pragma unroll
        for (int o = 16; o; o >>= 1) ss += __shfl_down_sync(~0u, ss, o);
        if ((tid & 31) == 0) red[tid >> 5] = ss;
        __syncthreads();
        if (tid < 8) {
            ss = red[tid];
#pragma unroll
            for (int o = 4; o; o >>= 1) ss += __shfl_down_sync(0xffu, ss, o);
            if (tid == 0) normp[(b * 768 + ch) * 2 + half] = ss;
        }
    }
}

// ================= fused pos path per 16-row slab =================
__global__ void __launch_bounds__(128) pos_slab(
    const float* __restrict__ v, const float* __restrict__ w1,
    const float* __restrict__ w2, float* __restrict__ out) {
    __shared__ float inb[20][128];
    __shared__ float mid[18][132];
    const int blk = blockIdx.x;
    const int s = blk & 7;
    const int ch = (blk >> 3) % CDIM;
    const int b = blk / (CDIM * 8);
    const int y0 = s * 16;
    const int tid = threadIdx.x;
    const float* ip = v + ((size_t)b * C3 + 768 + ch) * NPIX;

    for (int i = tid; i < 20 * 32; i += 128) {
        int r = i >> 5, c4 = (i & 31) * 4;
        int y = y0 - 2 + r;
        float4 val = (y >= 0 && y <= 127) ? *(const float4*)(ip + y * 128 + c4)
                                          : make_float4(0.f, 0.f, 0.f, 0.f);
        *(float4*)&inb[r][c4] = val;
    }
    __syncthreads();

    {
        const float* wp = w1 + ch * 9;
        float w00 = wp[0], w01 = wp[1], w02 = wp[2];
        float w10 = wp[3], w11 = wp[4], w12 = wp[5];
        float w20 = wp[6], w21 = wp[7], w22 = wp[8];
        for (int i = tid; i < 18 * 32; i += 128) {
            int r = i >> 5, c4 = (i & 31) * 4;
            int m = y0 - 1 + r;
            float o0 = 0.f, o1 = 0.f, o2 = 0.f, o3 = 0.f;
            if (m >= 0 && m <= 127) {
#pragma unroll
                for (int ky = 0; ky < 3; ky++) {
                    int yy = m + ky - 1;
                    if (yy < 0 || yy > 127) continue;
                    const float* rp = inb[r + ky];
                    float4 c = *(const float4*)(rp + c4);
                    float lft = (c4 > 0) ? rp[c4 - 1] : 0.f;
                    float rgt = (c4 < 124) ? rp[c4 + 4] : 0.f;
                    float wa = (ky == 0) ? w00 : (ky == 1) ? w10 : w20;
                    float wb = (ky == 0) ? w01 : (ky == 1) ? w11 : w21;
                    float wc = (ky == 0) ? w02 : (ky == 1) ? w12 : w22;
                    o0 += wa * lft + wb * c.x + wc * c.y;
                    o1 += wa * c.x + wb * c.y + wc * c.z;
                    o2 += wa * c.y + wb * c.z + wc * c.w;
                    o3 += wa * c.z + wb * c.w + wc * rgt;
                }
                o0 = 0.5f * o0 * (1.0f + erff(o0 * 0.70710678118654752f));
                o1 = 0.5f * o1 * (1.0f + erff(o1 * 0.70710678118654752f));
                o2 = 0.5f * o2 * (1.0f + erff(o2 * 0.70710678118654752f));
                o3 = 0.5f * o3 * (1.0f + erff(o3 * 0.70710678118654752f));
            }
            mid[r][c4] = o0; mid[r][c4 + 1] = o1;
            mid[r][c4 + 2] = o2; mid[r][c4 + 3] = o3;
        }
    }
    __syncthreads();

    {
        const float* wp = w2 + ch * 9;
        float w00 = wp[0], w01 = wp[1], w02 = wp[2];
        float w10 = wp[3], w11 = wp[4], w12 = wp[5];
        float w20 = wp[6], w21 = wp[7], w22 = wp[8];
        float* op = out + ((size_t)b * CDIM + ch) * NPIX;
        for (int i = tid; i < 16 * 32; i += 128) {
            int j = i >> 5, c4 = (i & 31) * 4;
            int y = y0 + j;
            float o0 = 0.f, o1 = 0.f, o2 = 0.f, o3 = 0.f;
#pragma unroll
            for (int ky = 0; ky < 3; ky++) {
                const float* rp = mid[j + ky];
                float c0 = rp[c4], c1 = rp[c4 + 1], c2 = rp[c4 + 2], c3 = rp[c4 + 3];
                float lft = (c4 > 0) ? rp[c4 - 1] : 0.f;
                float rgt = (c4 < 124) ? rp[c4 + 4] : 0.f;
                float wa = (ky == 0) ? w00 : (ky == 1) ? w10 : w20;
                float wb = (ky == 0) ? w01 : (ky == 1) ? w11 : w21;
                float wc = (ky == 0) ? w02 : (ky == 1) ? w12 : w22;
                o0 += wa * lft + wb * c0 + wc * c1;
                o1 += wa * c0 + wb * c1 + wc * c2;
                o2 += wa * c1 + wb * c2 + wc * c3;
                o3 += wa * c2 + wb * c3 + wc * rgt;
            }
            float4 prev = *(const float4*)(op + y * 128 + c4);
            *(float4*)(op + y * 128 + c4) =
                make_float4(prev.x + o0, prev.y + o1, prev.z + o2, prev.w + o3);
        }
    }
}

// ================= q.k^T partials (32 splits of 512 px) =================
__global__ void attn_partial(const float* __restrict__ qkv, float* __restrict__ part) {
    __shared__ float qs[48][68];
    __shared__ float ks[48][68];
    const int split = blockIdx.x, h = blockIdx.y, b = blockIdx.z;
    const int tid = threadIdx.x;
    const float* qbase = qkv + ((size_t)b * C3 + h * CPH) * NPIX;
    const float* kbase = qkv + ((size_t)b * C3 + 384 + h * CPH) * NPIX;
    const int tx = tid & 15, ty = tid >> 4;
    const int c0 = ty * 3, d0 = tx * 3;
    float acc[3][3];
#pragma unroll
    for (int i = 0; i < 3; i++)
#pragma unroll
        for (int j = 0; j < 3; j++) acc[i][j] = 0.f;

    for (int chunk = 0; chunk < 8; chunk++) {
        int n0 = split * 512 + chunk * 64;
        __syncthreads();
#pragma unroll
        for (int r = 0; r < 3; r++) {
            int v = tid + r * 256;
            int row = v >> 4;
            int col = (v & 15) << 2;
            *(float4*)&qs[row][col] = *(const float4*)(qbase + (size_t)row * NPIX + n0 + col);
            *(float4*)&ks[row][col] = *(const float4*)(kbase + (size_t)row * NPIX + n0 + col);
        }
        __syncthreads();
#pragma unroll
        for (int i = 0; i < 64; i += 4) {
            float4 q0 = *(const float4*)&qs[c0][i];
            float4 q1 = *(const float4*)&qs[c0 + 1][i];
            float4 q2 = *(const float4*)&qs[c0 + 2][i];
            float4 k0 = *(const float4*)&ks[d0][i];
            float4 k1 = *(const float4*)&ks[d0 + 1][i];
            float4 k2 = *(const float4*)&ks[d0 + 2][i];
            acc[0][0] += q0.x * k0.x + q0.y * k0.y + q0.z * k0.z + q0.w * k0.w;
            acc[0][1] += q0.x * k1.x + q0.y * k1.y + q0.z * k1.z + q0.w * k1.w;
            acc[0][2] += q0.x * k2.x + q0.y * k2.y + q0.z * k2.z + q0.w * k2.w;
            acc[1][0] += q1.x * k0.x + q1.y * k0.y + q1.z * k0.z + q1.w * k0.w;
            acc[1][1] += q1.x * k1.x + q1.y * k1.y + q1.z * k1.z + q1.w * k1.w;
            acc[1][2] += q1.x * k2.x + q1.y * k2.y + q1.z * k2.z + q1.w * k2.w;
            acc[2][0] += q2.x * k0.x + q2.y * k0.y + q2.z * k0.z + q2.w * k0.w;
            acc[2][1] += q2.x * k1.x + q2.y * k1.y + q2.z * k1.z + q2.w * k1.w;
            acc[2][2] += q2.x * k2.x + q2.y * k2.y + q2.z * k2.z + q2.w * k2.w;
        }
    }
    float* pp = part + ((size_t)((b * NHEADS + h) * 32 + split)) * 2304;
#pragma unroll
    for (int i = 0; i < 3; i++)
#pragma unroll
        for (int j = 0; j < 3; j++) pp[(c0 + i) * 48 + d0 + j] = acc[i][j];
}

// ================= fused: reduce partials -> logits -> dual softmax blend =================
__global__ void attn_finish(const float* __restrict__ part, const float* __restrict__ normp,
                            const float* __restrict__ temp, const int* __restrict__ mask,
                            const float* __restrict__ wb, float* __restrict__ probs) {
    int row = blockIdx.x;
    int c = row % 48;
    int h = (row / 48) % NHEADS;
    int b = row / (48 * NHEADS);
    int bh = b * NHEADS + h;
    int lane = threadIdx.x;
    const int* mp = mask + (h * 48 + c) * 48;
    int qidx = b * 768 + h * CPH + c;
    float inq = 1.0f / fmaxf(sqrtf(normp[qidx * 2] + normp[qidx * 2 + 1]), 1e-12f);
    float tmp = temp[h];

    float lg[2];
#pragma unroll
    for (int t = 0; t < 2; t++) {
        int d = lane + t * 32;
        if (d < 48) {
            float s = 0.f;
#pragma unroll
            for (int sp = 0; sp < 32; sp++)
                s += part[((size_t)(bh * 32 + sp)) * 2304 + c * 48 + d];
            int kidx = b * 768 + 384 + h * CPH + d;
            float ink = 1.0f / fmaxf(sqrtf(normp[kidx * 2] + normp[kidx * 2 + 1]), 1e-12f);
            lg[t] = s * inq * ink * tmp;
        } else {
            lg[t] = -INFINITY;
        }
    }
    bool v1ok = lane + 32 < 48;
    float a0 = lg[0], a1 = lg[1];
    float b0 = (mp[lane] == 0) ? -1e9f : a0;
    float b1 = v1ok ? ((mp[lane + 32] == 0) ? -1e9f : a1) : -INFINITY;
    float mA = fmaxf(a0, a1), mB = fmaxf(b0, b1);
#pragma unroll
    for (int o = 16; o; o >>= 1) {
        mA = fmaxf(mA, __shfl_xor_sync(~0u, mA, o));
        mB = fmaxf(mB, __shfl_xor_sync(~0u, mB, o));
    }
    float eA0 = expf(a0 - mA);
    float eA1 = v1ok ? expf(a1 - mA) : 0.f;
    float eB0 = expf(b0 - mB);
    float eB1 = v1ok ? expf(b1 - mB) : 0.f;
    float sA = eA0 + eA1, sB = eB0 + eB1;
#pragma unroll
    for (int o = 16; o; o >>= 1) {
        sA += __shfl_xor_sync(~0u, sA, o);
        sB += __shfl_xor_sync(~0u, sB, o);
    }
    float w0 = wb[0], w1 = wb[1];
    float wm = fmaxf(w0, w1);
    float ew0 = expf(w0 - wm), ew1 = expf(w1 - wm);
    float wsum = ew0 + ew1;
    float blend0 = ew0 / wsum, blend1 = ew1 / wsum;
    float* pp = probs + (size_t)row * 48;
    pp[lane] = blend0 * eA0 / sA + blend1 * eB0 / sB;
    if (v1ok) pp[lane + 32] = blend0 * eA1 / sA + blend1 * eB1 / sB;
}

// ================= out = attn @ v -> transposed bf16 hi/lo (coalesced) =================
__global__ void attnv(const float* __restrict__ probs, const float* __restrict__ qkv2,
                      __nv_bfloat16* __restrict__ th, __nv_bfloat16* __restrict__ tl) {
    __shared__ float a_s[2304];
    __shared__ uint32_t sh[2][128][26];
    const int h = blockIdx.y, b = blockIdx.z;
    const int tid = threadIdx.x;
    const int n0 = blockIdx.x * 128;
    const int n = n0 + tid;
    const float* ap = probs + (size_t)(b * NHEADS + h) * 2304;
    for (int i = tid; i < 2304; i += 128) a_s[i] = ap[i];
    __syncthreads();
    const float* vbase = qkv2 + ((size_t)b * C3 + 768 + h * CPH) * NPIX + n;
    float vr[48];
#pragma unroll
    for (int d = 0; d < 48; d++) vr[d] = vbase[(size_t)d * NPIX];
    float accv[48];
#pragma unroll 4
    for (int c = 0; c < 48; c++) {
        float acc = 0.f;
#pragma unroll
        for (int d = 0; d < 48; d++) acc += a_s[c * 48 + d] * vr[d];
        accv[c] = acc;
    }
#pragma unroll
    for (int c2 = 0; c2 < 24; c2++) {
        float v0 = accv[2 * c2], v1 = accv[2 * c2 + 1];
        __nv_bfloat16 h0 = __float2bfloat16_rn(v0);
        __nv_bfloat16 h1 = __float2bfloat16_rn(v1);
        __nv_bfloat16 l0 = __float2bfloat16_rn(v0 - __bfloat162float(h0));
        __nv_bfloat16 l1 = __float2bfloat16_rn(v1 - __bfloat162float(h1));
        sh[0][tid][c2] = (uint32_t)__bfloat16_as_ushort(h0) |
                         ((uint32_t)__bfloat16_as_ushort(h1) << 16);
        sh[1][tid][c2] = (uint32_t)__bfloat16_as_ushort(l0) |
                         ((uint32_t)__bfloat16_as_ushort(l1) << 16);
    }
    __syncthreads();
    for (int idx = tid; idx < 2 * 128 * 12; idx += 128) {
        int a = idx / (128 * 12);
        int r = (idx / 12) & 127;
        int j = idx % 12;
        uint2 v = *(const uint2*)&sh[a][r][j * 2];
        __nv_bfloat16* base = a ? tl : th;
        *((uint2*)(base + ((size_t)b * NPIX + n0 + r) * CDIM + h * CPH) + j) = v;
    }
}

// ================= launch =================
extern "C" void kernel_launch(void* const* d_in, const int* in_sizes, int n_in,
                              void* d_out, int out_size) {
    const float* x           = (const float*)d_in[0];
    const int*   mask        = (const int*)d_in[1];
    const float* qkv_w       = (const float*)d_in[2];
    const float* dw_w        = (const float*)d_in[3];
    const float* proj_w      = (const float*)d_in[4];
    const float* temperature = (const float*)d_in[5];
    const float* w_blend     = (const float*)d_in[6];
    const float* pos_w1      = (const float*)d_in[7];
    const float* pos_w2      = (const float*)d_in[8];
    float* out = (float*)d_out;

    __half* qkv1h;
    float *qkv2, *normp, *part, *probs;
    __nv_bfloat16 *xh, *xl, *ah, *al, *wqh, *wql, *wph, *wpl;
    cudaGetSymbolAddress((void**)&qkv1h, g_qkv1h);
    cudaGetSymbolAddress((void**)&qkv2, g_qkv2);
    cudaGetSymbolAddress((void**)&normp, g_normp);
    cudaGetSymbolAddress((void**)&part, g_part);
    cudaGetSymbolAddress((void**)&probs, g_probs);
    cudaGetSymbolAddress((void**)&xh, g_xT_hi);
    cudaGetSymbolAddress((void**)&xl, g_xT_lo);
    cudaGetSymbolAddress((void**)&ah, g_aT_hi);
    cudaGetSymbolAddress((void**)&al, g_aT_lo);
    cudaGetSymbolAddress((void**)&wqh, g_wq_hi);
    cudaGetSymbolAddress((void**)&wql, g_wq_lo);
    cudaGetSymbolAddress((void**)&wph, g_wp_hi);
    cudaGetSymbolAddress((void**)&wpl, g_wp_lo);

    static bool init_done = false;
    if (!init_done) {
        cudaFuncSetAttribute(gemm_hmma<float>, cudaFuncAttributeMaxDynamicSharedMemorySize,
                             GEMM_SMEM);
        cudaFuncSetAttribute(gemm_hmma<__half>, cudaFuncAttributeMaxDynamicSharedMemorySize,
                             GEMM_SMEM);
        cudaFuncSetAttribute(dwconv_half, cudaFuncAttributeMaxDynamicSharedMemorySize,
                             66 * 128 * 4);
        init_done = true;
    }

    // 0) operand conversion
    cvt_split<<<(C3 * CDIM + 255) / 256, 256>>>(qkv_w, wqh, wql, C3 * CDIM);
    cvt_split<<<(CDIM * CDIM + 255) / 256, 256>>>(proj_w, wph, wpl, CDIM * CDIM);
    transpose_split2<<<dim3(NPIX / 64, CDIM / 64, BATCH), 256>>>(x, xh, xl);

    // 1) qkv 1x1 conv via HMMA -> fp16 intermediate
    gemm_hmma<__half><<<dim3(C3 / 128, NPIX / 128, BATCH), 128, GEMM_SMEM>>>(
        wqh, wql, xh, xl, qkv1h, (size_t)NPIX * CDIM, (size_t)C3 * NPIX);

    // 2) depthwise 3x3 (half-channel, fp16 in) + norm partials
    dwconv_half<<<BATCH * C3 * 2, 256, 66 * 128 * 4>>>(qkv1h, dw_w, qkv2, normp);

    // 3) q.k^T partials (32 splits), then fused reduce + dual softmax
    attn_partial<<<dim3(32, NHEADS, BATCH), 256>>>(qkv2, part);
    attn_finish<<<BATCH * NHEADS * 48, 32>>>(part, normp, temperature, mask, w_blend, probs);

    // 4) attn @ v -> transposed bf16 hi/lo
    attnv<<<dim3(NPIX / 128, NHEADS, BATCH), 128>>>(probs, qkv2, ah, al);

    // 5) proj 1x1 conv via HMMA (writes d_out, fp32)
    gemm_hmma<float><<<dim3(CDIM / 128, NPIX / 128, BATCH), 128, GEMM_SMEM>>>(
        wph, wpl, ah, al, out, (size_t)NPIX * CDIM, (size_t)CDIM * NPIX);

    // 6) fused pos path (slab), adds into d_out
    pos_slab<<<BATCH * CDIM * 8, 128>>>(qkv2, pos_w1, pos_w2, out);
}